// round 13
// baseline (speedup 1.0000x reference)
#include <cuda_runtime.h>
#include <cuda_fp16.h>
#include <cstdint>
#include <cstddef>

#define NATOM 100000
#define C2F 256
#define NROWS 1200000
#define A2_TILES 18750     /* 1.2M rows / 64 */
#define A2_SLOTS 148       /* grid.x; grid.y=2 -> 296 blocks (2/SM) */
#define G1_TILES 782       /* ceil(100000/128) */
#define PC_BLOCKS 1250
#define NBR_BLKS 75000     /* NROWS*16 float4 / 256 */

// ---------------- scratch (device globals; no allocation) ----------------
__device__ __align__(16) __half g_T1h[(size_t)NATOM*C2F];
__device__ __align__(16) __half g_T2h[(size_t)NATOM*C2F];
__device__ __align__(16) __half g_Gh[(size_t)NROWS*C2F];
__device__ __align__(16) __half g_Xh[(size_t)NROWS*64];
__device__ __align__(16) float  g_S [(size_t)NATOM*128];
__device__ int   g_idx32[NROWS];
__device__ float g_p1s[296*128], g_p1q[296*128];
__device__ float g_part2[PC_BLOCKS*256];
__device__ __align__(16) float g_a1[C2F], g_c1[C2F];
__device__ __align__(16) float g_a2[128], g_c2[128];
__device__ unsigned int g_cnt1 = 0;
__device__ unsigned int g_cnt2 = 0;

// ---------------- helpers ----------------
__device__ __forceinline__ uint32_t smem_u32(const void* p) {
    uint32_t a;
    asm("{ .reg .u64 t; cvta.to.shared.u64 t, %1; cvt.u32.u64 %0, t; }" : "=r"(a) : "l"(p));
    return a;
}
__device__ __forceinline__ uint32_t f2h2(float a, float b) {
    __half2 h = __floats2half2_rn(a, b);
    return *reinterpret_cast<uint32_t*>(&h);
}
__device__ __forceinline__ void mma16(float d[4],
    uint32_t a0, uint32_t a1, uint32_t a2, uint32_t a3,
    uint32_t b0, uint32_t b1) {
    asm volatile(
        "mma.sync.aligned.m16n8k16.row.col.f32.f16.f16.f32 "
        "{%0,%1,%2,%3}, {%4,%5,%6,%7}, {%8,%9}, {%0,%1,%2,%3};"
        : "+f"(d[0]), "+f"(d[1]), "+f"(d[2]), "+f"(d[3])
        : "r"(a0), "r"(a1), "r"(a2), "r"(a3), "r"(b0), "r"(b1));
}
#define LDSM4(r0, r1, r2, r3, addr) \
    asm volatile("ldmatrix.sync.aligned.m8n8.x4.shared.b16 {%0,%1,%2,%3}, [%4];" \
        : "=r"(r0), "=r"(r1), "=r"(r2), "=r"(r3) : "r"(addr))
#define CPA16(dst, src) \
    asm volatile("cp.async.cg.shared.global [%0], [%1], 16;" :: "r"(dst), "l"(src) : "memory")
#define CPA_COMMIT() asm volatile("cp.async.commit_group;" ::: "memory")
#define CPA_WAIT0()  asm volatile("cp.async.wait_group 0;" ::: "memory")
#define CPA_WAIT1()  asm volatile("cp.async.wait_group 1;" ::: "memory")

// feature permutation within a 16-group: real offset u -> smem row offset
__device__ __forceinline__ int perm16(int u) {
    return ((u >> 1) & 1) * 8 + (u >> 2) * 2 + (u & 1);
}

// ---------------- kernel P: fused nbr->fp16 + idx convert -----------------
__global__ __launch_bounds__(256)
void pre_kernel(const float* __restrict__ nbr, const void* __restrict__ idx_raw) {
    const int b = blockIdx.x;
    if (b < NBR_BLKS) {
        const size_t i = (size_t)b * 256 + threadIdx.x;   // float4 index
        float4 x = __ldcs((const float4*)nbr + i);
        *(uint2*)(g_Xh + i*4) = make_uint2(f2h2(x.x, x.y), f2h2(x.z, x.w));
    } else {
        __shared__ int s_is64;
        if (threadIdx.x == 0) {
            const unsigned int* w = (const unsigned int*)idx_raw;
            int f = 1;
            for (int i2 = 0; i2 < 128; i2++) if (w[2*i2 + 1] != 0u) { f = 0; break; }
            s_is64 = f;
        }
        __syncthreads();
        const int i = (b - NBR_BLKS) * 256 + threadIdx.x;
        if (i < NROWS) {
            if (s_is64) g_idx32[i] = (int)((const long long*)idx_raw)[i];
            else        g_idx32[i] = ((const int*)idx_raw)[i];
        }
    }
}

// ---------------- kernel 2: GEMM1 big (y-loop inside; X staged once) -------
__global__ __launch_bounds__(512, 2)
void gemm1_mma(const float* __restrict__ atom, const float* __restrict__ W) {
    extern __shared__ char smraw[];
    __half* Xs = (__half*)smraw;                 // [128][136]
    __half* Ws = (__half*)(smraw + 128*136*2);   // [128][136] feature-permuted
    const int tid = threadIdx.x;
    const int wid = tid >> 5, l = tid & 31;
    const int l4 = l >> 2, lm = l & 3;
    const int wr = wid & 3, wc = wid >> 2;
    const int r0 = blockIdx.x * 128;

    for (int e = tid; e < 128*32; e += 512) {
        int r = e >> 5, q = e & 31;
        int gr = r0 + r;
        float4 x = make_float4(0.f, 0.f, 0.f, 0.f);
        if (gr < NATOM) x = *(const float4*)(atom + (size_t)gr*128 + q*4);
        *(uint2*)(Xs + r*136 + q*4) = make_uint2(f2h2(x.x, x.y), f2h2(x.z, x.w));
    }

    const int lrow = (l & 7) + ((l >> 3) & 1) * 8;
    const uint32_t lk = (uint32_t)((l >> 4) << 4);
    const uint32_t sX = smem_u32(Xs), sW = smem_u32(Ws);
    uint32_t aoff[2], boff[2];
    aoff[0] = sX + (uint32_t)(wr*32 + lrow) * 272u + lk;
    aoff[1] = aoff[0] + 16u * 272u;
    boff[0] = sW + (uint32_t)(wc*32 + lrow) * 272u + lk;
    boff[1] = boff[0] + 16u * 272u;

    for (int y = 0; y < 4; y++) {
        for (int e = tid; e < 128*32; e += 512) {
            int i = e >> 5, q = e & 31;
            int s = (i & ~15) + perm16(i & 15);
            const float* src = (y < 2) ? (W + (size_t)(y*128 + i)*320 + q*4)
                                       : (W + (size_t)((y - 2)*128 + i)*320 + 128 + q*4);
            float4 x = *(const float4*)src;
            *(uint2*)(Ws + s*136 + q*4) = make_uint2(f2h2(x.x, x.y), f2h2(x.z, x.w));
        }
        __syncthreads();

        float c[2][4][4];
#pragma unroll
        for (int m = 0; m < 2; m++)
#pragma unroll
            for (int n = 0; n < 4; n++)
#pragma unroll
                for (int e = 0; e < 4; e++) c[m][n][e] = 0.f;

#pragma unroll
        for (int kki = 0; kki < 8; kki++) {
            uint32_t a[2][4], b[4][2];
            LDSM4(a[0][0], a[0][1], a[0][2], a[0][3], aoff[0] + kki*32);
            LDSM4(a[1][0], a[1][1], a[1][2], a[1][3], aoff[1] + kki*32);
            LDSM4(b[0][0], b[1][0], b[0][1], b[1][1], boff[0] + kki*32);
            LDSM4(b[2][0], b[3][0], b[2][1], b[3][1], boff[1] + kki*32);
#pragma unroll
            for (int m = 0; m < 2; m++)
#pragma unroll
                for (int n = 0; n < 4; n++)
                    mma16(c[m][n], a[m][0], a[m][1], a[m][2], a[m][3], b[n][0], b[n][1]);
        }

        __half* dst = (y < 2) ? g_T1h : g_T2h;
        const int coff = (y & 1) * 128;
#pragma unroll
        for (int m = 0; m < 2; m++) {
            int rl = wr*32 + m*16 + l4;
            int gr = r0 + rl;
#pragma unroll
            for (int p = 0; p < 2; p++) {
                int cl = coff + wc*32 + p*16 + 4*lm;
                if (gr < NATOM)
                    *(uint2*)&dst[(size_t)gr*256 + cl] =
                        make_uint2(f2h2(c[m][2*p][0], c[m][2*p][1]),
                                   f2h2(c[m][2*p+1][0], c[m][2*p+1][1]));
                if (gr + 8 < NATOM)
                    *(uint2*)&dst[(size_t)(gr + 8)*256 + cl] =
                        make_uint2(f2h2(c[m][2*p][2], c[m][2*p][3]),
                                   f2h2(c[m][2*p+1][2], c[m][2*p+1][3]));
            }
        }
        __syncthreads();
    }
}

// ---------------- kernel 3: A2 (fp16 mma, ldmatrix, 3-stage cp.async) ------
// T1 read via __ldg in epilogue (L1/L2-hot, 12x reuse). g_Gh stored with .cs
// (evict-first) so the 614MB write stream doesn't evict the T2h gather set.
#define SM_WE  0                         /* half [128][72]     = 18432 */
#define SM_X   18432                     /* half [3][64][72]   = 27648 */
#define SM_T2  46080                     /* half [3][64][144]  = 55296 */
#define SM_IX  101376                    /* int  [4][64]       =  1024 */
#define SM_RED 102400                    /* float[2][2][128]   =  2048 */
#define SM_A2_TOTAL 104448

__global__ __launch_bounds__(512, 2)
void a2_mma(const float* __restrict__ W, const float* __restrict__ bias,
            const float* __restrict__ gamma1, const float* __restrict__ beta1) {
    extern __shared__ char smraw[];
    __half* We  = (__half*)(smraw + SM_WE);
    float*  red_s = (float*)(smraw + SM_RED);
    float*  red_q = red_s + 256;
    const uint32_t sbase = smem_u32(smraw);

    const int tid = threadIdx.x;
    const int wid = tid >> 5, l = tid & 31;
    const int l4 = l >> 2, lm = l & 3;
    const int wr = wid & 1, wc = wid >> 1;
    const int bx = blockIdx.x, h = blockIdx.y;
    const int coff = h * 128;

    for (int e = tid; e < 128*16; e += 512) {
        int o = e >> 4, q = e & 15;
        int s = (o & ~15) + perm16(o & 15);
        float4 x = *(const float4*)(W + (size_t)(coff + o)*320 + 256 + q*4);
        *(uint2*)(We + s*72 + q*4) = make_uint2(f2h2(x.x, x.y), f2h2(x.z, x.w));
    }
    const float4 bb = *(const float4*)(bias + coff + wc*16 + 4*lm);

    const int* idxs = (const int*)(smraw + SM_IX);
    const int kmax = (A2_TILES - 1 - bx) / A2_SLOTS;

#define ISSUE_DATA(TT, BUF, IDXP) do { \
    const int _r0 = (TT) * 64; \
    { int r = tid >> 3, q = tid & 7; \
      CPA16(sbase + SM_X + (uint32_t)(BUF)*9216u + (uint32_t)(r*144 + q*16), \
            (const char*)(g_Xh + (size_t)(_r0 + r)*64 + q*8)); } \
    for (int e = tid; e < 1024; e += 512) { \
        int r = e >> 4, q = e & 15; \
        CPA16(sbase + SM_T2 + (uint32_t)(BUF)*18432u + (uint32_t)(r*288 + q*16), \
              (const char*)(g_T2h + (size_t)(IDXP)[r]*256 + coff + q*8)); \
    } \
} while (0)

#define ISSUE_IDX(TT, SLOT) do { \
    if (tid < 16) CPA16(sbase + SM_IX + (uint32_t)(SLOT)*256u + (uint32_t)tid*16u, \
                        (const char*)(g_idx32 + (size_t)(TT)*64) + tid*16); \
} while (0)

    ISSUE_IDX(bx, 0);
    ISSUE_IDX(bx + A2_SLOTS, 1);
    CPA_COMMIT(); CPA_WAIT0(); __syncthreads();

    ISSUE_DATA(bx, 0, idxs);
    ISSUE_IDX(bx + 2*A2_SLOTS, 2);
    CPA_COMMIT();
    ISSUE_DATA(bx + A2_SLOTS, 1, idxs + 64);
    ISSUE_IDX(bx + 3*A2_SLOTS, 3);
    CPA_COMMIT();

    uint32_t Bf[4][2][2];
#pragma unroll
    for (int kki = 0; kki < 4; kki++)
#pragma unroll
        for (int n = 0; n < 2; n++) {
            int o = wc*16 + n*8 + l4;
            Bf[kki][n][0] = *(uint32_t*)&We[o*72 + kki*16 + 2*lm];
            Bf[kki][n][1] = *(uint32_t*)&We[o*72 + kki*16 + 8 + 2*lm];
        }

    const int lrow = (l & 7) + ((l >> 3) & 1) * 8;
    const uint32_t lk = (uint32_t)((l >> 4) << 4);
    uint32_t aoff0 = (uint32_t)((wr*32 + lrow) * 144) + lk;

    float accS[4], accQ[4];
#pragma unroll
    for (int i = 0; i < 4; i++) { accS[i] = 0.f; accQ[i] = 0.f; }

    const int f0 = wc*16 + 4*lm;

    for (int k = 0; ; k++) {
        CPA_WAIT1();
        __syncthreads();

        if (k + 2 <= kmax) {
            const int tt = bx + (k + 2)*A2_SLOTS;
            ISSUE_DATA(tt, (k + 2) % 3, idxs + ((k + 2) & 3)*64);
            if (k + 4 <= kmax) ISSUE_IDX(bx + (k + 4)*A2_SLOTS, (k + 4) & 3);
        }
        CPA_COMMIT();

        const int buf = k % 3;
        const uint32_t xaddr = sbase + SM_X + (uint32_t)buf*9216u;
        const __half* T2p = (const __half*)(smraw + SM_T2 + buf*18432u);
        const int r0 = (bx + k*A2_SLOTS) * 64;

        float c[2][2][4];
#pragma unroll
        for (int m = 0; m < 2; m++)
#pragma unroll
            for (int n = 0; n < 2; n++)
#pragma unroll
                for (int e = 0; e < 4; e++) c[m][n][e] = 0.f;

#pragma unroll
        for (int kki = 0; kki < 4; kki++) {
            uint32_t a0, a1, a2, a3;
            LDSM4(a0, a1, a2, a3, xaddr + aoff0 + kki*32);
            mma16(c[0][0], a0, a1, a2, a3, Bf[kki][0][0], Bf[kki][0][1]);
            mma16(c[0][1], a0, a1, a2, a3, Bf[kki][1][0], Bf[kki][1][1]);
            LDSM4(a0, a1, a2, a3, xaddr + aoff0 + 16u*144u + kki*32);
            mma16(c[1][0], a0, a1, a2, a3, Bf[kki][0][0], Bf[kki][0][1]);
            mma16(c[1][1], a0, a1, a2, a3, Bf[kki][1][0], Bf[kki][1][1]);
        }

#pragma unroll
        for (int m = 0; m < 2; m++) {
            const int rlA = wr*32 + m*16 + l4;
            const int rlB = rlA + 8;
            {
                uint2 u1 = __ldg((const uint2*)&g_T1h[(size_t)((r0 + rlA)/12)*256 + coff + f0]);
                uint2 u2 = *(const uint2*)&T2p[rlA*144 + f0];
                float2 t1a = __half22float2(*(__half2*)&u1.x);
                float2 t1b = __half22float2(*(__half2*)&u1.y);
                float2 t2a = __half22float2(*(__half2*)&u2.x);
                float2 t2b = __half22float2(*(__half2*)&u2.y);
                float y0 = c[m][0][0] + t1a.x + t2a.x + bb.x;
                float y1 = c[m][0][1] + t1a.y + t2a.y + bb.y;
                float y2 = c[m][1][0] + t1b.x + t2b.x + bb.z;
                float y3 = c[m][1][1] + t1b.y + t2b.y + bb.w;
                __stcs((uint2*)&g_Gh[(size_t)(r0 + rlA)*256 + coff + f0],
                       make_uint2(f2h2(y0, y1), f2h2(y2, y3)));
                accS[0] += y0; accQ[0] += y0*y0;
                accS[1] += y1; accQ[1] += y1*y1;
                accS[2] += y2; accQ[2] += y2*y2;
                accS[3] += y3; accQ[3] += y3*y3;
            }
            {
                uint2 u1 = __ldg((const uint2*)&g_T1h[(size_t)((r0 + rlB)/12)*256 + coff + f0]);
                uint2 u2 = *(const uint2*)&T2p[rlB*144 + f0];
                float2 t1a = __half22float2(*(__half2*)&u1.x);
                float2 t1b = __half22float2(*(__half2*)&u1.y);
                float2 t2a = __half22float2(*(__half2*)&u2.x);
                float2 t2b = __half22float2(*(__half2*)&u2.y);
                float y0 = c[m][0][2] + t1a.x + t2a.x + bb.x;
                float y1 = c[m][0][3] + t1a.y + t2a.y + bb.y;
                float y2 = c[m][1][2] + t1b.x + t2b.x + bb.z;
                float y3 = c[m][1][3] + t1b.y + t2b.y + bb.w;
                __stcs((uint2*)&g_Gh[(size_t)(r0 + rlB)*256 + coff + f0],
                       make_uint2(f2h2(y0, y1), f2h2(y2, y3)));
                accS[0] += y0; accQ[0] += y0*y0;
                accS[1] += y1; accQ[1] += y1*y1;
                accS[2] += y2; accQ[2] += y2*y2;
                accS[3] += y3; accQ[3] += y3*y3;
            }
        }

        if (k == kmax) break;
    }

    // ---- BN1 partial reduction ----
#pragma unroll
    for (int off = 4; off < 32; off <<= 1) {
#pragma unroll
        for (int i = 0; i < 4; i++) {
            accS[i] += __shfl_xor_sync(0xffffffffu, accS[i], off);
            accQ[i] += __shfl_xor_sync(0xffffffffu, accQ[i], off);
        }
    }
    __syncthreads();
    if (l < 4) {
#pragma unroll
        for (int u = 0; u < 4; u++) {
            int f = wc*16 + 4*l + u;
            red_s[wr*128 + f] = accS[u];
            red_q[wr*128 + f] = accQ[u];
        }
    }
    __syncthreads();
    if (tid < 128) {
        float s = red_s[tid] + red_s[128 + tid];
        float q = red_q[tid] + red_q[128 + tid];
        g_p1s[(h*A2_SLOTS + bx)*128 + tid] = s;
        g_p1q[(h*A2_SLOTS + bx)*128 + tid] = q;
    }

    // ---- fused BN1 finalize ----
    __threadfence();
    __shared__ unsigned int s_rank;
    __syncthreads();
    if (tid == 0) s_rank = atomicAdd(&g_cnt1, 1u);
    __syncthreads();
    if (s_rank == 295u) {
        if (tid < 256) {
            const int F = tid, hh = F >> 7, fl = F & 127;
            float s = 0.f, q = 0.f;
            for (int b2 = 0; b2 < A2_SLOTS; b2++) {
                s += g_p1s[(hh*A2_SLOTS + b2)*128 + fl];
                q += g_p1q[(hh*A2_SLOTS + b2)*128 + fl];
            }
            const float mean = s * (1.0f / (float)NROWS);
            const float var  = q * (1.0f / (float)NROWS) - mean*mean;
            const float inv  = rsqrtf(var + 1e-5f);
            g_a1[F] = inv * gamma1[F];
            g_c1[F] = beta1[F] - mean * inv * gamma1[F];
        }
        __syncthreads();
        if (tid == 0) atomicExch(&g_cnt1, 0u);
    }
}

// ---------------- kernel 5: pass C + fused BN2 finalize --------------------
__device__ __forceinline__ float sigrelu(float xf, float xc) {
    float r = fmaxf(xc, 0.f);
    float e = __expf(-xf);
    return __fdividef(r, 1.0f + e);
}

__global__ __launch_bounds__(256)
void passC_kernel(const float* __restrict__ gamma2, const float* __restrict__ beta2) {
    __shared__ float wsum[8*128], wsq[8*128];
    const int tid = threadIdx.x, wid = tid >> 5, l = tid & 31;
    const float4 af = *(const float4*)(g_a1 + l*4);
    const float4 cf = *(const float4*)(g_c1 + l*4);
    const float4 ac = *(const float4*)(g_a1 + 128 + l*4);
    const float4 cc = *(const float4*)(g_c1 + 128 + l*4);
    float4 ts = make_float4(0.f, 0.f, 0.f, 0.f);
    float4 tq = make_float4(0.f, 0.f, 0.f, 0.f);

    for (int it = 0; it < 10; it++) {
        const int n = blockIdx.x*80 + it*8 + wid;
        float4 acc = make_float4(0.f, 0.f, 0.f, 0.f);
#pragma unroll
        for (int m = 0; m < 12; m++) {
            const size_t base = ((size_t)n*12 + m) * 256;
            uint2 uf = __ldcs((const uint2*)(g_Gh + base + l*4));
            uint2 uc = __ldcs((const uint2*)(g_Gh + base + 128 + l*4));
            float2 f01 = __half22float2(*(__half2*)&uf.x);
            float2 f23 = __half22float2(*(__half2*)&uf.y);
            float2 c01 = __half22float2(*(__half2*)&uc.x);
            float2 c23 = __half22float2(*(__half2*)&uc.y);
            acc.x += sigrelu(f01.x*af.x + cf.x, c01.x*ac.x + cc.x);
            acc.y += sigrelu(f01.y*af.y + cf.y, c01.y*ac.y + cc.y);
            acc.z += sigrelu(f23.x*af.z + cf.z, c23.x*ac.z + cc.z);
            acc.w += sigrelu(f23.y*af.w + cf.w, c23.y*ac.w + cc.w);
        }
        *(float4*)(g_S + (size_t)n*128 + l*4) = acc;
        ts.x += acc.x; ts.y += acc.y; ts.z += acc.z; ts.w += acc.w;
        tq.x += acc.x*acc.x; tq.y += acc.y*acc.y; tq.z += acc.z*acc.z; tq.w += acc.w*acc.w;
    }
    wsum[wid*128 + l*4 + 0] = ts.x; wsum[wid*128 + l*4 + 1] = ts.y;
    wsum[wid*128 + l*4 + 2] = ts.z; wsum[wid*128 + l*4 + 3] = ts.w;
    wsq [wid*128 + l*4 + 0] = tq.x; wsq [wid*128 + l*4 + 1] = tq.y;
    wsq [wid*128 + l*4 + 2] = tq.z; wsq [wid*128 + l*4 + 3] = tq.w;
    __syncthreads();
    if (tid < 128) {
        float s = 0.f, q = 0.f;
#pragma unroll
        for (int u = 0; u < 8; u++) { s += wsum[u*128 + tid]; q += wsq[u*128 + tid]; }
        g_part2[blockIdx.x*256 + tid]       = s;
        g_part2[blockIdx.x*256 + 128 + tid] = q;
    }

    // ---- fused BN2 finalize: last-finishing block computes g_a2/g_c2 ----
    __threadfence();
    __shared__ unsigned int s_rank;
    __syncthreads();
    if (tid == 0) s_rank = atomicAdd(&g_cnt2, 1u);
    __syncthreads();
    if (s_rank == PC_BLOCKS - 1u) {
        const int col = tid & 127, seg = tid >> 7;   // 2 segments
        float s = 0.f, q = 0.f;
        for (int b = seg; b < PC_BLOCKS; b += 2) {
            s += g_part2[b*256 + col];
            q += g_part2[b*256 + 128 + col];
        }
        wsum[seg*128 + col] = s; wsq[seg*128 + col] = q;
        __syncthreads();
        if (tid < 128) {
            s = wsum[tid] + wsum[128 + tid];
            q = wsq[tid] + wsq[128 + tid];
            const float mean = s * (1.0f / (float)NATOM);
            const float var  = q * (1.0f / (float)NATOM) - mean*mean;
            const float inv  = rsqrtf(var + 1e-5f);
            g_a2[tid] = inv * gamma2[tid];
            g_c2[tid] = beta2[tid] - mean * inv * gamma2[tid];
        }
        __syncthreads();
        if (tid == 0) atomicExch(&g_cnt2, 0u);
    }
}

// ---------------- kernel 7: residual + relu --------------------------------
__global__ void final_kernel(const float* __restrict__ atom, float* __restrict__ out) {
    const int i = blockIdx.x * blockDim.x + threadIdx.x;
    if (i >= NATOM * 32) return;
    const int o = (i & 31) * 4;
    const float4 a = *(const float4*)(g_a2 + o);
    const float4 c = *(const float4*)(g_c2 + o);
    const float4 v = ((const float4*)atom)[i];
    const float4 s = ((const float4*)g_S)[i];
    float4 r;
    r.x = fmaxf(v.x + s.x*a.x + c.x, 0.f);
    r.y = fmaxf(v.y + s.y*a.y + c.y, 0.f);
    r.z = fmaxf(v.z + s.z*a.z + c.z, 0.f);
    r.w = fmaxf(v.w + s.w*a.w + c.w, 0.f);
    ((float4*)out)[i] = r;
}

// ---------------- launch ----------------------------------------------------
extern "C" void kernel_launch(void* const* d_in, const int* in_sizes, int n_in,
                              void* d_out, int out_size) {
    (void)in_sizes; (void)n_in; (void)out_size;
    const float* atom = (const float*)d_in[0];
    const float* nbr  = (const float*)d_in[1];
    const void*  idx  = d_in[2];
    const float* W    = (const float*)d_in[3];
    const float* b    = (const float*)d_in[4];
    const float* g1   = (const float*)d_in[5];
    const float* b1   = (const float*)d_in[6];
    const float* g2   = (const float*)d_in[7];
    const float* b2   = (const float*)d_in[8];
    float* out = (float*)d_out;

    const int smemG1 = 2 * 128 * 136 * 2;   // 69632
    const int smemA2 = SM_A2_TOTAL;         // 104448
    cudaFuncSetAttribute(gemm1_mma, cudaFuncAttributeMaxDynamicSharedMemorySize, smemG1);
    cudaFuncSetAttribute(a2_mma,    cudaFuncAttributeMaxDynamicSharedMemorySize, smemA2);

    static cudaStream_t s1 = nullptr, s2 = nullptr;
    static cudaEvent_t ev0 = nullptr, ev1 = nullptr, ev2 = nullptr;
    if (s1 == nullptr) {
        cudaStreamCreateWithFlags(&s1, cudaStreamNonBlocking);
        cudaStreamCreateWithFlags(&s2, cudaStreamNonBlocking);
        cudaEventCreateWithFlags(&ev0, cudaEventDisableTiming);
        cudaEventCreateWithFlags(&ev1, cudaEventDisableTiming);
        cudaEventCreateWithFlags(&ev2, cudaEventDisableTiming);
    }

    cudaEventRecord(ev0, 0);
    cudaStreamWaitEvent(s1, ev0, 0);
    cudaStreamWaitEvent(s2, ev0, 0);

    pre_kernel<<<NBR_BLKS + (NROWS + 255)/256, 256, 0, s2>>>(nbr, idx);
    gemm1_mma<<<G1_TILES, 512, smemG1, s1>>>(atom, W);

    cudaEventRecord(ev1, s1);
    cudaEventRecord(ev2, s2);
    cudaStreamWaitEvent(0, ev1, 0);
    cudaStreamWaitEvent(0, ev2, 0);

    a2_mma<<<dim3(A2_SLOTS, 2), 512, smemA2>>>(W, b, g1, b1);
    passC_kernel<<<PC_BLOCKS, 256>>>(g2, b2);
    final_kernel<<<12500, 256>>>(atom, out);
}

// round 14
// speedup vs baseline: 1.0524x; 1.0524x over previous
#include <cuda_runtime.h>
#include <cuda_fp16.h>
#include <cstdint>
#include <cstddef>

#define NATOM 100000
#define C2F 256
#define NROWS 1200000
#define A2_TILES 18750     /* 1.2M rows / 64 */
#define A2_SLOTS 148       /* grid.x; grid.y=2 -> 296 blocks (2/SM) */
#define G1_TILES 782       /* ceil(100000/128) */
#define PC_BLOCKS 1250
#define NBR_BLKS 75000     /* NROWS*16 float4 / 256 */

// ---------------- scratch (device globals; no allocation) ----------------
__device__ __align__(16) __half g_T1h[(size_t)NATOM*C2F];
__device__ __align__(16) __half g_T2h[(size_t)NATOM*C2F];
__device__ __align__(16) __half g_Gh[(size_t)NROWS*C2F];
__device__ __align__(16) __half g_Xh[(size_t)NROWS*64];
__device__ __align__(16) float  g_S [(size_t)NATOM*128];
__device__ int   g_idx32[NROWS];
__device__ float g_p1s[296*128], g_p1q[296*128];
__device__ float g_part2[PC_BLOCKS*256];
__device__ __align__(16) float g_a1[C2F], g_c1[C2F];
__device__ __align__(16) float g_a2[128], g_c2[128];
__device__ unsigned int g_cnt1 = 0;
__device__ unsigned int g_cnt2 = 0;

// ---------------- helpers ----------------
__device__ __forceinline__ uint32_t smem_u32(const void* p) {
    uint32_t a;
    asm("{ .reg .u64 t; cvta.to.shared.u64 t, %1; cvt.u32.u64 %0, t; }" : "=r"(a) : "l"(p));
    return a;
}
__device__ __forceinline__ uint32_t f2h2(float a, float b) {
    __half2 h = __floats2half2_rn(a, b);
    return *reinterpret_cast<uint32_t*>(&h);
}
__device__ __forceinline__ void mma16(float d[4],
    uint32_t a0, uint32_t a1, uint32_t a2, uint32_t a3,
    uint32_t b0, uint32_t b1) {
    asm volatile(
        "mma.sync.aligned.m16n8k16.row.col.f32.f16.f16.f32 "
        "{%0,%1,%2,%3}, {%4,%5,%6,%7}, {%8,%9}, {%0,%1,%2,%3};"
        : "+f"(d[0]), "+f"(d[1]), "+f"(d[2]), "+f"(d[3])
        : "r"(a0), "r"(a1), "r"(a2), "r"(a3), "r"(b0), "r"(b1));
}
#define LDSM4(r0, r1, r2, r3, addr) \
    asm volatile("ldmatrix.sync.aligned.m8n8.x4.shared.b16 {%0,%1,%2,%3}, [%4];" \
        : "=r"(r0), "=r"(r1), "=r"(r2), "=r"(r3) : "r"(addr))
#define CPA16(dst, src) \
    asm volatile("cp.async.cg.shared.global [%0], [%1], 16;" :: "r"(dst), "l"(src) : "memory")
#define CPA_COMMIT() asm volatile("cp.async.commit_group;" ::: "memory")
#define CPA_WAIT0()  asm volatile("cp.async.wait_group 0;" ::: "memory")
#define CPA_WAIT1()  asm volatile("cp.async.wait_group 1;" ::: "memory")

// feature permutation within a 16-group: real offset u -> smem row offset
__device__ __forceinline__ int perm16(int u) {
    return ((u >> 1) & 1) * 8 + (u >> 2) * 2 + (u & 1);
}

// ---------------- kernel P: fused nbr->fp16 + idx convert -----------------
__global__ __launch_bounds__(256)
void pre_kernel(const float* __restrict__ nbr, const void* __restrict__ idx_raw) {
    const int b = blockIdx.x;
    if (b < NBR_BLKS) {
        const size_t i = (size_t)b * 256 + threadIdx.x;   // float4 index
        float4 x = __ldcs((const float4*)nbr + i);
        *(uint2*)(g_Xh + i*4) = make_uint2(f2h2(x.x, x.y), f2h2(x.z, x.w));
    } else {
        __shared__ int s_is64;
        if (threadIdx.x == 0) {
            const unsigned int* w = (const unsigned int*)idx_raw;
            int f = 1;
            for (int i2 = 0; i2 < 128; i2++) if (w[2*i2 + 1] != 0u) { f = 0; break; }
            s_is64 = f;
        }
        __syncthreads();
        const int i = (b - NBR_BLKS) * 256 + threadIdx.x;
        if (i < NROWS) {
            if (s_is64) g_idx32[i] = (int)((const long long*)idx_raw)[i];
            else        g_idx32[i] = ((const int*)idx_raw)[i];
        }
    }
}

// ---------------- kernel 2: GEMM1 big (y-loop inside; X staged once) -------
__global__ __launch_bounds__(512, 2)
void gemm1_mma(const float* __restrict__ atom, const float* __restrict__ W) {
    extern __shared__ char smraw[];
    __half* Xs = (__half*)smraw;                 // [128][136]
    __half* Ws = (__half*)(smraw + 128*136*2);   // [128][136] feature-permuted
    const int tid = threadIdx.x;
    const int wid = tid >> 5, l = tid & 31;
    const int l4 = l >> 2, lm = l & 3;
    const int wr = wid & 3, wc = wid >> 2;
    const int r0 = blockIdx.x * 128;

    for (int e = tid; e < 128*32; e += 512) {
        int r = e >> 5, q = e & 31;
        int gr = r0 + r;
        float4 x = make_float4(0.f, 0.f, 0.f, 0.f);
        if (gr < NATOM) x = *(const float4*)(atom + (size_t)gr*128 + q*4);
        *(uint2*)(Xs + r*136 + q*4) = make_uint2(f2h2(x.x, x.y), f2h2(x.z, x.w));
    }

    const int lrow = (l & 7) + ((l >> 3) & 1) * 8;
    const uint32_t lk = (uint32_t)((l >> 4) << 4);
    const uint32_t sX = smem_u32(Xs), sW = smem_u32(Ws);
    uint32_t aoff[2], boff[2];
    aoff[0] = sX + (uint32_t)(wr*32 + lrow) * 272u + lk;
    aoff[1] = aoff[0] + 16u * 272u;
    boff[0] = sW + (uint32_t)(wc*32 + lrow) * 272u + lk;
    boff[1] = boff[0] + 16u * 272u;

    for (int y = 0; y < 4; y++) {
        for (int e = tid; e < 128*32; e += 512) {
            int i = e >> 5, q = e & 31;
            int s = (i & ~15) + perm16(i & 15);
            const float* src = (y < 2) ? (W + (size_t)(y*128 + i)*320 + q*4)
                                       : (W + (size_t)((y - 2)*128 + i)*320 + 128 + q*4);
            float4 x = *(const float4*)src;
            *(uint2*)(Ws + s*136 + q*4) = make_uint2(f2h2(x.x, x.y), f2h2(x.z, x.w));
        }
        __syncthreads();

        float c[2][4][4];
#pragma unroll
        for (int m = 0; m < 2; m++)
#pragma unroll
            for (int n = 0; n < 4; n++)
#pragma unroll
                for (int e = 0; e < 4; e++) c[m][n][e] = 0.f;

#pragma unroll
        for (int kki = 0; kki < 8; kki++) {
            uint32_t a[2][4], b[4][2];
            LDSM4(a[0][0], a[0][1], a[0][2], a[0][3], aoff[0] + kki*32);
            LDSM4(a[1][0], a[1][1], a[1][2], a[1][3], aoff[1] + kki*32);
            LDSM4(b[0][0], b[1][0], b[0][1], b[1][1], boff[0] + kki*32);
            LDSM4(b[2][0], b[3][0], b[2][1], b[3][1], boff[1] + kki*32);
#pragma unroll
            for (int m = 0; m < 2; m++)
#pragma unroll
                for (int n = 0; n < 4; n++)
                    mma16(c[m][n], a[m][0], a[m][1], a[m][2], a[m][3], b[n][0], b[n][1]);
        }

        __half* dst = (y < 2) ? g_T1h : g_T2h;
        const int coff = (y & 1) * 128;
#pragma unroll
        for (int m = 0; m < 2; m++) {
            int rl = wr*32 + m*16 + l4;
            int gr = r0 + rl;
#pragma unroll
            for (int p = 0; p < 2; p++) {
                int cl = coff + wc*32 + p*16 + 4*lm;
                if (gr < NATOM)
                    *(uint2*)&dst[(size_t)gr*256 + cl] =
                        make_uint2(f2h2(c[m][2*p][0], c[m][2*p][1]),
                                   f2h2(c[m][2*p+1][0], c[m][2*p+1][1]));
                if (gr + 8 < NATOM)
                    *(uint2*)&dst[(size_t)(gr + 8)*256 + cl] =
                        make_uint2(f2h2(c[m][2*p][2], c[m][2*p][3]),
                                   f2h2(c[m][2*p+1][2], c[m][2*p+1][3]));
            }
        }
        __syncthreads();
    }
}

// ---------------- kernel 3: A2 (fp16 mma, ldmatrix, 3-stage cp.async) ------
// R12 configuration: T1 staged via cp.async, plain (default-cache) g_Gh stores.
#define SM_WE  0                         /* half [128][72]     = 18432 */
#define SM_X   18432                     /* half [3][64][72]   = 27648 */
#define SM_T2  46080                     /* half [3][64][144]  = 55296 */
#define SM_T1  101376                    /* half [3][8][144]   =  6912 */
#define SM_IX  108288                    /* int  [4][64]       =  1024 */
#define SM_RED 109312                    /* float[2][2][128]   =  2048 */
#define SM_A2_TOTAL 111360

__global__ __launch_bounds__(512, 2)
void a2_mma(const float* __restrict__ W, const float* __restrict__ bias,
            const float* __restrict__ gamma1, const float* __restrict__ beta1) {
    extern __shared__ char smraw[];
    __half* We  = (__half*)(smraw + SM_WE);
    float*  red_s = (float*)(smraw + SM_RED);
    float*  red_q = red_s + 256;
    const uint32_t sbase = smem_u32(smraw);

    const int tid = threadIdx.x;
    const int wid = tid >> 5, l = tid & 31;
    const int l4 = l >> 2, lm = l & 3;
    const int wr = wid & 1, wc = wid >> 1;
    const int bx = blockIdx.x, h = blockIdx.y;
    const int coff = h * 128;

    for (int e = tid; e < 128*16; e += 512) {
        int o = e >> 4, q = e & 15;
        int s = (o & ~15) + perm16(o & 15);
        float4 x = *(const float4*)(W + (size_t)(coff + o)*320 + 256 + q*4);
        *(uint2*)(We + s*72 + q*4) = make_uint2(f2h2(x.x, x.y), f2h2(x.z, x.w));
    }
    const float4 bb = *(const float4*)(bias + coff + wc*16 + 4*lm);

    const int* idxs = (const int*)(smraw + SM_IX);
    const int kmax = (A2_TILES - 1 - bx) / A2_SLOTS;

#define ISSUE_DATA(TT, BUF, IDXP) do { \
    const int _r0 = (TT) * 64; \
    const int _n0 = _r0 / 12; \
    const int _nc = (_r0 + 63) / 12 - _n0 + 1; \
    { int r = tid >> 3, q = tid & 7; \
      CPA16(sbase + SM_X + (uint32_t)(BUF)*9216u + (uint32_t)(r*144 + q*16), \
            (const char*)(g_Xh + (size_t)(_r0 + r)*64 + q*8)); } \
    for (int e = tid; e < 1024; e += 512) { \
        int r = e >> 4, q = e & 15; \
        CPA16(sbase + SM_T2 + (uint32_t)(BUF)*18432u + (uint32_t)(r*288 + q*16), \
              (const char*)(g_T2h + (size_t)(IDXP)[r]*256 + coff + q*8)); \
    } \
    for (int e = tid; e < _nc*16; e += 512) { \
        int j = e >> 4, q = e & 15; \
        CPA16(sbase + SM_T1 + (uint32_t)(BUF)*2304u + (uint32_t)(j*288 + q*16), \
              (const char*)(g_T1h + (size_t)(_n0 + j)*256 + coff + q*8)); \
    } \
} while (0)

#define ISSUE_IDX(TT, SLOT) do { \
    if (tid < 16) CPA16(sbase + SM_IX + (uint32_t)(SLOT)*256u + (uint32_t)tid*16u, \
                        (const char*)(g_idx32 + (size_t)(TT)*64) + tid*16); \
} while (0)

    ISSUE_IDX(bx, 0);
    ISSUE_IDX(bx + A2_SLOTS, 1);
    CPA_COMMIT(); CPA_WAIT0(); __syncthreads();

    ISSUE_DATA(bx, 0, idxs);
    ISSUE_IDX(bx + 2*A2_SLOTS, 2);
    CPA_COMMIT();
    ISSUE_DATA(bx + A2_SLOTS, 1, idxs + 64);
    ISSUE_IDX(bx + 3*A2_SLOTS, 3);
    CPA_COMMIT();

    uint32_t Bf[4][2][2];
#pragma unroll
    for (int kki = 0; kki < 4; kki++)
#pragma unroll
        for (int n = 0; n < 2; n++) {
            int o = wc*16 + n*8 + l4;
            Bf[kki][n][0] = *(uint32_t*)&We[o*72 + kki*16 + 2*lm];
            Bf[kki][n][1] = *(uint32_t*)&We[o*72 + kki*16 + 8 + 2*lm];
        }

    const int lrow = (l & 7) + ((l >> 3) & 1) * 8;
    const uint32_t lk = (uint32_t)((l >> 4) << 4);
    uint32_t aoff0 = (uint32_t)((wr*32 + lrow) * 144) + lk;

    float accS[4], accQ[4];
#pragma unroll
    for (int i = 0; i < 4; i++) { accS[i] = 0.f; accQ[i] = 0.f; }

    const int f0 = wc*16 + 4*lm;

    for (int k = 0; ; k++) {
        CPA_WAIT1();
        __syncthreads();

        if (k + 2 <= kmax) {
            const int tt = bx + (k + 2)*A2_SLOTS;
            ISSUE_DATA(tt, (k + 2) % 3, idxs + ((k + 2) & 3)*64);
            if (k + 4 <= kmax) ISSUE_IDX(bx + (k + 4)*A2_SLOTS, (k + 4) & 3);
        }
        CPA_COMMIT();

        const int buf = k % 3;
        const uint32_t xaddr = sbase + SM_X + (uint32_t)buf*9216u;
        const __half* T2p = (const __half*)(smraw + SM_T2 + buf*18432u);
        const __half* T1p = (const __half*)(smraw + SM_T1 + buf*2304u);
        const int r0 = (bx + k*A2_SLOTS) * 64;
        const int n0 = r0 / 12;

        float c[2][2][4];
#pragma unroll
        for (int m = 0; m < 2; m++)
#pragma unroll
            for (int n = 0; n < 2; n++)
#pragma unroll
                for (int e = 0; e < 4; e++) c[m][n][e] = 0.f;

#pragma unroll
        for (int kki = 0; kki < 4; kki++) {
            uint32_t a0, a1, a2, a3;
            LDSM4(a0, a1, a2, a3, xaddr + aoff0 + kki*32);
            mma16(c[0][0], a0, a1, a2, a3, Bf[kki][0][0], Bf[kki][0][1]);
            mma16(c[0][1], a0, a1, a2, a3, Bf[kki][1][0], Bf[kki][1][1]);
            LDSM4(a0, a1, a2, a3, xaddr + aoff0 + 16u*144u + kki*32);
            mma16(c[1][0], a0, a1, a2, a3, Bf[kki][0][0], Bf[kki][0][1]);
            mma16(c[1][1], a0, a1, a2, a3, Bf[kki][1][0], Bf[kki][1][1]);
        }

#pragma unroll
        for (int m = 0; m < 2; m++) {
            const int rlA = wr*32 + m*16 + l4;
            const int rlB = rlA + 8;
            const int nA = (r0 + rlA)/12 - n0;
            const int nB = (r0 + rlB)/12 - n0;
            {
                uint2 u1 = *(const uint2*)&T1p[nA*144 + f0];
                uint2 u2 = *(const uint2*)&T2p[rlA*144 + f0];
                float2 t1a = __half22float2(*(__half2*)&u1.x);
                float2 t1b = __half22float2(*(__half2*)&u1.y);
                float2 t2a = __half22float2(*(__half2*)&u2.x);
                float2 t2b = __half22float2(*(__half2*)&u2.y);
                float y0 = c[m][0][0] + t1a.x + t2a.x + bb.x;
                float y1 = c[m][0][1] + t1a.y + t2a.y + bb.y;
                float y2 = c[m][1][0] + t1b.x + t2b.x + bb.z;
                float y3 = c[m][1][1] + t1b.y + t2b.y + bb.w;
                *(uint2*)&g_Gh[(size_t)(r0 + rlA)*256 + coff + f0] =
                    make_uint2(f2h2(y0, y1), f2h2(y2, y3));
                accS[0] += y0; accQ[0] += y0*y0;
                accS[1] += y1; accQ[1] += y1*y1;
                accS[2] += y2; accQ[2] += y2*y2;
                accS[3] += y3; accQ[3] += y3*y3;
            }
            {
                uint2 u1 = *(const uint2*)&T1p[nB*144 + f0];
                uint2 u2 = *(const uint2*)&T2p[rlB*144 + f0];
                float2 t1a = __half22float2(*(__half2*)&u1.x);
                float2 t1b = __half22float2(*(__half2*)&u1.y);
                float2 t2a = __half22float2(*(__half2*)&u2.x);
                float2 t2b = __half22float2(*(__half2*)&u2.y);
                float y0 = c[m][0][2] + t1a.x + t2a.x + bb.x;
                float y1 = c[m][0][3] + t1a.y + t2a.y + bb.y;
                float y2 = c[m][1][2] + t1b.x + t2b.x + bb.z;
                float y3 = c[m][1][3] + t1b.y + t2b.y + bb.w;
                *(uint2*)&g_Gh[(size_t)(r0 + rlB)*256 + coff + f0] =
                    make_uint2(f2h2(y0, y1), f2h2(y2, y3));
                accS[0] += y0; accQ[0] += y0*y0;
                accS[1] += y1; accQ[1] += y1*y1;
                accS[2] += y2; accQ[2] += y2*y2;
                accS[3] += y3; accQ[3] += y3*y3;
            }
        }

        if (k == kmax) break;
    }

    // ---- BN1 partial reduction ----
#pragma unroll
    for (int off = 4; off < 32; off <<= 1) {
#pragma unroll
        for (int i = 0; i < 4; i++) {
            accS[i] += __shfl_xor_sync(0xffffffffu, accS[i], off);
            accQ[i] += __shfl_xor_sync(0xffffffffu, accQ[i], off);
        }
    }
    __syncthreads();
    if (l < 4) {
#pragma unroll
        for (int u = 0; u < 4; u++) {
            int f = wc*16 + 4*l + u;
            red_s[wr*128 + f] = accS[u];
            red_q[wr*128 + f] = accQ[u];
        }
    }
    __syncthreads();
    if (tid < 128) {
        float s = red_s[tid] + red_s[128 + tid];
        float q = red_q[tid] + red_q[128 + tid];
        g_p1s[(h*A2_SLOTS + bx)*128 + tid] = s;
        g_p1q[(h*A2_SLOTS + bx)*128 + tid] = q;
    }

    // ---- fused BN1 finalize ----
    __threadfence();
    __shared__ unsigned int s_rank;
    __syncthreads();
    if (tid == 0) s_rank = atomicAdd(&g_cnt1, 1u);
    __syncthreads();
    if (s_rank == 295u) {
        if (tid < 256) {
            const int F = tid, hh = F >> 7, fl = F & 127;
            float s = 0.f, q = 0.f;
            for (int b2 = 0; b2 < A2_SLOTS; b2++) {
                s += g_p1s[(hh*A2_SLOTS + b2)*128 + fl];
                q += g_p1q[(hh*A2_SLOTS + b2)*128 + fl];
            }
            const float mean = s * (1.0f / (float)NROWS);
            const float var  = q * (1.0f / (float)NROWS) - mean*mean;
            const float inv  = rsqrtf(var + 1e-5f);
            g_a1[F] = inv * gamma1[F];
            g_c1[F] = beta1[F] - mean * inv * gamma1[F];
        }
        __syncthreads();
        if (tid == 0) atomicExch(&g_cnt1, 0u);
    }
}

// ---------------- kernel 5: pass C + fused BN2 finalize --------------------
__device__ __forceinline__ float sigrelu(float xf, float xc) {
    float r = fmaxf(xc, 0.f);
    float e = __expf(-xf);
    return __fdividef(r, 1.0f + e);
}

__global__ __launch_bounds__(256)
void passC_kernel(const float* __restrict__ gamma2, const float* __restrict__ beta2) {
    __shared__ float wsum[8*128], wsq[8*128];
    const int tid = threadIdx.x, wid = tid >> 5, l = tid & 31;
    const float4 af = *(const float4*)(g_a1 + l*4);
    const float4 cf = *(const float4*)(g_c1 + l*4);
    const float4 ac = *(const float4*)(g_a1 + 128 + l*4);
    const float4 cc = *(const float4*)(g_c1 + 128 + l*4);
    float4 ts = make_float4(0.f, 0.f, 0.f, 0.f);
    float4 tq = make_float4(0.f, 0.f, 0.f, 0.f);

    for (int it = 0; it < 10; it++) {
        const int n = blockIdx.x*80 + it*8 + wid;
        float4 acc = make_float4(0.f, 0.f, 0.f, 0.f);
#pragma unroll
        for (int m = 0; m < 12; m++) {
            const size_t base = ((size_t)n*12 + m) * 256;
            uint2 uf = *(const uint2*)(g_Gh + base + l*4);
            uint2 uc = *(const uint2*)(g_Gh + base + 128 + l*4);
            float2 f01 = __half22float2(*(__half2*)&uf.x);
            float2 f23 = __half22float2(*(__half2*)&uf.y);
            float2 c01 = __half22float2(*(__half2*)&uc.x);
            float2 c23 = __half22float2(*(__half2*)&uc.y);
            acc.x += sigrelu(f01.x*af.x + cf.x, c01.x*ac.x + cc.x);
            acc.y += sigrelu(f01.y*af.y + cf.y, c01.y*ac.y + cc.y);
            acc.z += sigrelu(f23.x*af.z + cf.z, c23.x*ac.z + cc.z);
            acc.w += sigrelu(f23.y*af.w + cf.w, c23.y*ac.w + cc.w);
        }
        *(float4*)(g_S + (size_t)n*128 + l*4) = acc;
        ts.x += acc.x; ts.y += acc.y; ts.z += acc.z; ts.w += acc.w;
        tq.x += acc.x*acc.x; tq.y += acc.y*acc.y; tq.z += acc.z*acc.z; tq.w += acc.w*acc.w;
    }
    wsum[wid*128 + l*4 + 0] = ts.x; wsum[wid*128 + l*4 + 1] = ts.y;
    wsum[wid*128 + l*4 + 2] = ts.z; wsum[wid*128 + l*4 + 3] = ts.w;
    wsq [wid*128 + l*4 + 0] = tq.x; wsq [wid*128 + l*4 + 1] = tq.y;
    wsq [wid*128 + l*4 + 2] = tq.z; wsq [wid*128 + l*4 + 3] = tq.w;
    __syncthreads();
    if (tid < 128) {
        float s = 0.f, q = 0.f;
#pragma unroll
        for (int u = 0; u < 8; u++) { s += wsum[u*128 + tid]; q += wsq[u*128 + tid]; }
        g_part2[blockIdx.x*256 + tid]       = s;
        g_part2[blockIdx.x*256 + 128 + tid] = q;
    }

    // ---- fused BN2 finalize: last-finishing block computes g_a2/g_c2 ----
    __threadfence();
    __shared__ unsigned int s_rank;
    __syncthreads();
    if (tid == 0) s_rank = atomicAdd(&g_cnt2, 1u);
    __syncthreads();
    if (s_rank == PC_BLOCKS - 1u) {
        const int col = tid & 127, seg = tid >> 7;   // 2 segments
        float s = 0.f, q = 0.f;
        for (int b = seg; b < PC_BLOCKS; b += 2) {
            s += g_part2[b*256 + col];
            q += g_part2[b*256 + 128 + col];
        }
        wsum[seg*128 + col] = s; wsq[seg*128 + col] = q;
        __syncthreads();
        if (tid < 128) {
            s = wsum[tid] + wsum[128 + tid];
            q = wsq[tid] + wsq[128 + tid];
            const float mean = s * (1.0f / (float)NATOM);
            const float var  = q * (1.0f / (float)NATOM) - mean*mean;
            const float inv  = rsqrtf(var + 1e-5f);
            g_a2[tid] = inv * gamma2[tid];
            g_c2[tid] = beta2[tid] - mean * inv * gamma2[tid];
        }
        __syncthreads();
        if (tid == 0) atomicExch(&g_cnt2, 0u);
    }
}

// ---------------- kernel 7: residual + relu --------------------------------
__global__ void final_kernel(const float* __restrict__ atom, float* __restrict__ out) {
    const int i = blockIdx.x * blockDim.x + threadIdx.x;
    if (i >= NATOM * 32) return;
    const int o = (i & 31) * 4;
    const float4 a = *(const float4*)(g_a2 + o);
    const float4 c = *(const float4*)(g_c2 + o);
    const float4 v = ((const float4*)atom)[i];
    const float4 s = ((const float4*)g_S)[i];
    float4 r;
    r.x = fmaxf(v.x + s.x*a.x + c.x, 0.f);
    r.y = fmaxf(v.y + s.y*a.y + c.y, 0.f);
    r.z = fmaxf(v.z + s.z*a.z + c.z, 0.f);
    r.w = fmaxf(v.w + s.w*a.w + c.w, 0.f);
    ((float4*)out)[i] = r;
}

// ---------------- launch ----------------------------------------------------
extern "C" void kernel_launch(void* const* d_in, const int* in_sizes, int n_in,
                              void* d_out, int out_size) {
    (void)in_sizes; (void)n_in; (void)out_size;
    const float* atom = (const float*)d_in[0];
    const float* nbr  = (const float*)d_in[1];
    const void*  idx  = d_in[2];
    const float* W    = (const float*)d_in[3];
    const float* b    = (const float*)d_in[4];
    const float* g1   = (const float*)d_in[5];
    const float* b1   = (const float*)d_in[6];
    const float* g2   = (const float*)d_in[7];
    const float* b2   = (const float*)d_in[8];
    float* out = (float*)d_out;

    const int smemG1 = 2 * 128 * 136 * 2;   // 69632
    const int smemA2 = SM_A2_TOTAL;         // 111360
    cudaFuncSetAttribute(gemm1_mma, cudaFuncAttributeMaxDynamicSharedMemorySize, smemG1);
    cudaFuncSetAttribute(a2_mma,    cudaFuncAttributeMaxDynamicSharedMemorySize, smemA2);

    static cudaStream_t s1 = nullptr, s2 = nullptr;
    static cudaEvent_t ev0 = nullptr, ev1 = nullptr, ev2 = nullptr;
    if (s1 == nullptr) {
        cudaStreamCreateWithFlags(&s1, cudaStreamNonBlocking);
        cudaStreamCreateWithFlags(&s2, cudaStreamNonBlocking);
        cudaEventCreateWithFlags(&ev0, cudaEventDisableTiming);
        cudaEventCreateWithFlags(&ev1, cudaEventDisableTiming);
        cudaEventCreateWithFlags(&ev2, cudaEventDisableTiming);
    }

    cudaEventRecord(ev0, 0);
    cudaStreamWaitEvent(s1, ev0, 0);
    cudaStreamWaitEvent(s2, ev0, 0);

    pre_kernel<<<NBR_BLKS + (NROWS + 255)/256, 256, 0, s2>>>(nbr, idx);
    gemm1_mma<<<G1_TILES, 512, smemG1, s1>>>(atom, W);

    cudaEventRecord(ev1, s1);
    cudaEventRecord(ev2, s2);
    cudaStreamWaitEvent(0, ev1, 0);
    cudaStreamWaitEvent(0, ev2, 0);

    a2_mma<<<dim3(A2_SLOTS, 2), 512, smemA2>>>(W, b, g1, b1);
    passC_kernel<<<PC_BLOCKS, 256>>>(g2, b2);
    final_kernel<<<12500, 256>>>(atom, out);
}

// round 15
// speedup vs baseline: 1.0733x; 1.0198x over previous
#include <cuda_runtime.h>
#include <cuda_fp16.h>
#include <cstdint>
#include <cstddef>

#define NATOM 100000
#define C2F 256
#define NROWS 1200000
#define A2_TILES 18750     /* 1.2M rows / 64 */
#define A2_SLOTS 148       /* grid.x; grid.y=2 -> 296 blocks (2/SM) */
#define G1_TILES 782       /* ceil(100000/128) */
#define PC_BLOCKS 1250
#define NBR_BLKS 75000     /* NROWS*16 float4 / 256 */

// ---------------- scratch (device globals; no allocation) ----------------
__device__ __align__(16) __half g_T1h[(size_t)NATOM*C2F];
__device__ __align__(16) __half g_T2h[(size_t)NATOM*C2F];
__device__ __align__(16) __half g_Gh[(size_t)NROWS*C2F];
__device__ __align__(16) __half g_Xh[(size_t)NROWS*64];
__device__ __align__(16) float  g_S [(size_t)NATOM*128];
__device__ int   g_idx32[NROWS];
__device__ float g_p1s[296*128], g_p1q[296*128];
__device__ float g_part2[PC_BLOCKS*256];
__device__ __align__(16) float g_a1[C2F], g_c1[C2F];
__device__ __align__(16) float g_a2[128], g_c2[128];
__device__ unsigned int g_cnt1 = 0;

// ---------------- helpers ----------------
__device__ __forceinline__ uint32_t smem_u32(const void* p) {
    uint32_t a;
    asm("{ .reg .u64 t; cvta.to.shared.u64 t, %1; cvt.u32.u64 %0, t; }" : "=r"(a) : "l"(p));
    return a;
}
__device__ __forceinline__ uint32_t f2h2(float a, float b) {
    __half2 h = __floats2half2_rn(a, b);
    return *reinterpret_cast<uint32_t*>(&h);
}
__device__ __forceinline__ void mma16(float d[4],
    uint32_t a0, uint32_t a1, uint32_t a2, uint32_t a3,
    uint32_t b0, uint32_t b1) {
    asm volatile(
        "mma.sync.aligned.m16n8k16.row.col.f32.f16.f16.f32 "
        "{%0,%1,%2,%3}, {%4,%5,%6,%7}, {%8,%9}, {%0,%1,%2,%3};"
        : "+f"(d[0]), "+f"(d[1]), "+f"(d[2]), "+f"(d[3])
        : "r"(a0), "r"(a1), "r"(a2), "r"(a3), "r"(b0), "r"(b1));
}
#define LDSM4(r0, r1, r2, r3, addr) \
    asm volatile("ldmatrix.sync.aligned.m8n8.x4.shared.b16 {%0,%1,%2,%3}, [%4];" \
        : "=r"(r0), "=r"(r1), "=r"(r2), "=r"(r3) : "r"(addr))
#define CPA16(dst, src) \
    asm volatile("cp.async.cg.shared.global [%0], [%1], 16;" :: "r"(dst), "l"(src) : "memory")
#define CPA_COMMIT() asm volatile("cp.async.commit_group;" ::: "memory")
#define CPA_WAIT0()  asm volatile("cp.async.wait_group 0;" ::: "memory")
#define CPA_WAIT1()  asm volatile("cp.async.wait_group 1;" ::: "memory")

// feature permutation within a 16-group: real offset u -> smem row offset
__device__ __forceinline__ int perm16(int u) {
    return ((u >> 1) & 1) * 8 + (u >> 2) * 2 + (u & 1);
}

// ---------------- kernel P: fused nbr->fp16 + idx convert -----------------
__global__ __launch_bounds__(256)
void pre_kernel(const float* __restrict__ nbr, const void* __restrict__ idx_raw) {
    const int b = blockIdx.x;
    if (b < NBR_BLKS) {
        const size_t i = (size_t)b * 256 + threadIdx.x;   // float4 index
        float4 x = __ldcs((const float4*)nbr + i);
        *(uint2*)(g_Xh + i*4) = make_uint2(f2h2(x.x, x.y), f2h2(x.z, x.w));
    } else {
        __shared__ int s_is64;
        if (threadIdx.x == 0) {
            const unsigned int* w = (const unsigned int*)idx_raw;
            int f = 1;
            for (int i2 = 0; i2 < 128; i2++) if (w[2*i2 + 1] != 0u) { f = 0; break; }
            s_is64 = f;
        }
        __syncthreads();
        const int i = (b - NBR_BLKS) * 256 + threadIdx.x;
        if (i < NROWS) {
            if (s_is64) g_idx32[i] = (int)((const long long*)idx_raw)[i];
            else        g_idx32[i] = ((const int*)idx_raw)[i];
        }
    }
}

// ---------------- kernel 2: GEMM1 big (y-loop inside; X staged once) -------
__global__ __launch_bounds__(512, 2)
void gemm1_mma(const float* __restrict__ atom, const float* __restrict__ W) {
    extern __shared__ char smraw[];
    __half* Xs = (__half*)smraw;                 // [128][136]
    __half* Ws = (__half*)(smraw + 128*136*2);   // [128][136] feature-permuted
    const int tid = threadIdx.x;
    const int wid = tid >> 5, l = tid & 31;
    const int l4 = l >> 2, lm = l & 3;
    const int wr = wid & 3, wc = wid >> 2;
    const int r0 = blockIdx.x * 128;

    for (int e = tid; e < 128*32; e += 512) {
        int r = e >> 5, q = e & 31;
        int gr = r0 + r;
        float4 x = make_float4(0.f, 0.f, 0.f, 0.f);
        if (gr < NATOM) x = *(const float4*)(atom + (size_t)gr*128 + q*4);
        *(uint2*)(Xs + r*136 + q*4) = make_uint2(f2h2(x.x, x.y), f2h2(x.z, x.w));
    }

    const int lrow = (l & 7) + ((l >> 3) & 1) * 8;
    const uint32_t lk = (uint32_t)((l >> 4) << 4);
    const uint32_t sX = smem_u32(Xs), sW = smem_u32(Ws);
    uint32_t aoff[2], boff[2];
    aoff[0] = sX + (uint32_t)(wr*32 + lrow) * 272u + lk;
    aoff[1] = aoff[0] + 16u * 272u;
    boff[0] = sW + (uint32_t)(wc*32 + lrow) * 272u + lk;
    boff[1] = boff[0] + 16u * 272u;

    for (int y = 0; y < 4; y++) {
        for (int e = tid; e < 128*32; e += 512) {
            int i = e >> 5, q = e & 31;
            int s = (i & ~15) + perm16(i & 15);
            const float* src = (y < 2) ? (W + (size_t)(y*128 + i)*320 + q*4)
                                       : (W + (size_t)((y - 2)*128 + i)*320 + 128 + q*4);
            float4 x = *(const float4*)src;
            *(uint2*)(Ws + s*136 + q*4) = make_uint2(f2h2(x.x, x.y), f2h2(x.z, x.w));
        }
        __syncthreads();

        float c[2][4][4];
#pragma unroll
        for (int m = 0; m < 2; m++)
#pragma unroll
            for (int n = 0; n < 4; n++)
#pragma unroll
                for (int e = 0; e < 4; e++) c[m][n][e] = 0.f;

#pragma unroll
        for (int kki = 0; kki < 8; kki++) {
            uint32_t a[2][4], b[4][2];
            LDSM4(a[0][0], a[0][1], a[0][2], a[0][3], aoff[0] + kki*32);
            LDSM4(a[1][0], a[1][1], a[1][2], a[1][3], aoff[1] + kki*32);
            LDSM4(b[0][0], b[1][0], b[0][1], b[1][1], boff[0] + kki*32);
            LDSM4(b[2][0], b[3][0], b[2][1], b[3][1], boff[1] + kki*32);
#pragma unroll
            for (int m = 0; m < 2; m++)
#pragma unroll
                for (int n = 0; n < 4; n++)
                    mma16(c[m][n], a[m][0], a[m][1], a[m][2], a[m][3], b[n][0], b[n][1]);
        }

        __half* dst = (y < 2) ? g_T1h : g_T2h;
        const int coff = (y & 1) * 128;
#pragma unroll
        for (int m = 0; m < 2; m++) {
            int rl = wr*32 + m*16 + l4;
            int gr = r0 + rl;
#pragma unroll
            for (int p = 0; p < 2; p++) {
                int cl = coff + wc*32 + p*16 + 4*lm;
                if (gr < NATOM)
                    *(uint2*)&dst[(size_t)gr*256 + cl] =
                        make_uint2(f2h2(c[m][2*p][0], c[m][2*p][1]),
                                   f2h2(c[m][2*p+1][0], c[m][2*p+1][1]));
                if (gr + 8 < NATOM)
                    *(uint2*)&dst[(size_t)(gr + 8)*256 + cl] =
                        make_uint2(f2h2(c[m][2*p][2], c[m][2*p][3]),
                                   f2h2(c[m][2*p+1][2], c[m][2*p+1][3]));
            }
        }
        __syncthreads();
    }
}

// ---------------- kernel 3: A2 (fp16 mma, ldmatrix, 3-stage cp.async) ------
// R12 config + smem-staged g_Gh stores: epilogue writes y back into the
// consumed T2 slot (1:1 per-thread mapping), then one coalesced uint4 burst.
#define SM_WE  0                         /* half [128][72]     = 18432 */
#define SM_X   18432                     /* half [3][64][72]   = 27648 */
#define SM_T2  46080                     /* half [3][64][144]  = 55296 */
#define SM_T1  101376                    /* half [3][8][144]   =  6912 */
#define SM_IX  108288                    /* int  [4][64]       =  1024 */
#define SM_RED 109312                    /* float[2][2][128]   =  2048 */
#define SM_A2_TOTAL 111360

__global__ __launch_bounds__(512, 2)
void a2_mma(const float* __restrict__ W, const float* __restrict__ bias,
            const float* __restrict__ gamma1, const float* __restrict__ beta1) {
    extern __shared__ char smraw[];
    __half* We  = (__half*)(smraw + SM_WE);
    float*  red_s = (float*)(smraw + SM_RED);
    float*  red_q = red_s + 256;
    const uint32_t sbase = smem_u32(smraw);

    const int tid = threadIdx.x;
    const int wid = tid >> 5, l = tid & 31;
    const int l4 = l >> 2, lm = l & 3;
    const int wr = wid & 1, wc = wid >> 1;
    const int bx = blockIdx.x, h = blockIdx.y;
    const int coff = h * 128;

    for (int e = tid; e < 128*16; e += 512) {
        int o = e >> 4, q = e & 15;
        int s = (o & ~15) + perm16(o & 15);
        float4 x = *(const float4*)(W + (size_t)(coff + o)*320 + 256 + q*4);
        *(uint2*)(We + s*72 + q*4) = make_uint2(f2h2(x.x, x.y), f2h2(x.z, x.w));
    }
    const float4 bb = *(const float4*)(bias + coff + wc*16 + 4*lm);

    const int* idxs = (const int*)(smraw + SM_IX);
    const int kmax = (A2_TILES - 1 - bx) / A2_SLOTS;

#define ISSUE_DATA(TT, BUF, IDXP) do { \
    const int _r0 = (TT) * 64; \
    const int _n0 = _r0 / 12; \
    const int _nc = (_r0 + 63) / 12 - _n0 + 1; \
    { int r = tid >> 3, q = tid & 7; \
      CPA16(sbase + SM_X + (uint32_t)(BUF)*9216u + (uint32_t)(r*144 + q*16), \
            (const char*)(g_Xh + (size_t)(_r0 + r)*64 + q*8)); } \
    for (int e = tid; e < 1024; e += 512) { \
        int r = e >> 4, q = e & 15; \
        CPA16(sbase + SM_T2 + (uint32_t)(BUF)*18432u + (uint32_t)(r*288 + q*16), \
              (const char*)(g_T2h + (size_t)(IDXP)[r]*256 + coff + q*8)); \
    } \
    for (int e = tid; e < _nc*16; e += 512) { \
        int j = e >> 4, q = e & 15; \
        CPA16(sbase + SM_T1 + (uint32_t)(BUF)*2304u + (uint32_t)(j*288 + q*16), \
              (const char*)(g_T1h + (size_t)(_n0 + j)*256 + coff + q*8)); \
    } \
} while (0)

#define ISSUE_IDX(TT, SLOT) do { \
    if (tid < 16) CPA16(sbase + SM_IX + (uint32_t)(SLOT)*256u + (uint32_t)tid*16u, \
                        (const char*)(g_idx32 + (size_t)(TT)*64) + tid*16); \
} while (0)

    ISSUE_IDX(bx, 0);
    ISSUE_IDX(bx + A2_SLOTS, 1);
    CPA_COMMIT(); CPA_WAIT0(); __syncthreads();

    ISSUE_DATA(bx, 0, idxs);
    ISSUE_IDX(bx + 2*A2_SLOTS, 2);
    CPA_COMMIT();
    ISSUE_DATA(bx + A2_SLOTS, 1, idxs + 64);
    ISSUE_IDX(bx + 3*A2_SLOTS, 3);
    CPA_COMMIT();

    uint32_t Bf[4][2][2];
#pragma unroll
    for (int kki = 0; kki < 4; kki++)
#pragma unroll
        for (int n = 0; n < 2; n++) {
            int o = wc*16 + n*8 + l4;
            Bf[kki][n][0] = *(uint32_t*)&We[o*72 + kki*16 + 2*lm];
            Bf[kki][n][1] = *(uint32_t*)&We[o*72 + kki*16 + 8 + 2*lm];
        }

    const int lrow = (l & 7) + ((l >> 3) & 1) * 8;
    const uint32_t lk = (uint32_t)((l >> 4) << 4);
    uint32_t aoff0 = (uint32_t)((wr*32 + lrow) * 144) + lk;

    float accS[4], accQ[4];
#pragma unroll
    for (int i = 0; i < 4; i++) { accS[i] = 0.f; accQ[i] = 0.f; }

    const int f0 = wc*16 + 4*lm;

    for (int k = 0; ; k++) {
        CPA_WAIT1();
        __syncthreads();

        if (k + 2 <= kmax) {
            const int tt = bx + (k + 2)*A2_SLOTS;
            ISSUE_DATA(tt, (k + 2) % 3, idxs + ((k + 2) & 3)*64);
            if (k + 4 <= kmax) ISSUE_IDX(bx + (k + 4)*A2_SLOTS, (k + 4) & 3);
        }
        CPA_COMMIT();

        const int buf = k % 3;
        const uint32_t xaddr = sbase + SM_X + (uint32_t)buf*9216u;
        __half* T2p = (__half*)(smraw + SM_T2 + buf*18432u);
        const __half* T1p = (const __half*)(smraw + SM_T1 + buf*2304u);
        const int r0 = (bx + k*A2_SLOTS) * 64;
        const int n0 = r0 / 12;

        float c[2][2][4];
#pragma unroll
        for (int m = 0; m < 2; m++)
#pragma unroll
            for (int n = 0; n < 2; n++)
#pragma unroll
                for (int e = 0; e < 4; e++) c[m][n][e] = 0.f;

#pragma unroll
        for (int kki = 0; kki < 4; kki++) {
            uint32_t a0, a1, a2, a3;
            LDSM4(a0, a1, a2, a3, xaddr + aoff0 + kki*32);
            mma16(c[0][0], a0, a1, a2, a3, Bf[kki][0][0], Bf[kki][0][1]);
            mma16(c[0][1], a0, a1, a2, a3, Bf[kki][1][0], Bf[kki][1][1]);
            LDSM4(a0, a1, a2, a3, xaddr + aoff0 + 16u*144u + kki*32);
            mma16(c[1][0], a0, a1, a2, a3, Bf[kki][0][0], Bf[kki][0][1]);
            mma16(c[1][1], a0, a1, a2, a3, Bf[kki][1][0], Bf[kki][1][1]);
        }

        // epilogue: y written back into the consumed T2 slot (same address
        // each thread just read -> no cross-thread hazard), then burst-store.
#pragma unroll
        for (int m = 0; m < 2; m++) {
            const int rlA = wr*32 + m*16 + l4;
            const int rlB = rlA + 8;
            const int nA = (r0 + rlA)/12 - n0;
            const int nB = (r0 + rlB)/12 - n0;
            {
                uint2 u1 = *(const uint2*)&T1p[nA*144 + f0];
                uint2 u2 = *(const uint2*)&T2p[rlA*144 + f0];
                float2 t1a = __half22float2(*(__half2*)&u1.x);
                float2 t1b = __half22float2(*(__half2*)&u1.y);
                float2 t2a = __half22float2(*(__half2*)&u2.x);
                float2 t2b = __half22float2(*(__half2*)&u2.y);
                float y0 = c[m][0][0] + t1a.x + t2a.x + bb.x;
                float y1 = c[m][0][1] + t1a.y + t2a.y + bb.y;
                float y2 = c[m][1][0] + t1b.x + t2b.x + bb.z;
                float y3 = c[m][1][1] + t1b.y + t2b.y + bb.w;
                *(uint2*)&T2p[rlA*144 + f0] = make_uint2(f2h2(y0, y1), f2h2(y2, y3));
                accS[0] += y0; accQ[0] += y0*y0;
                accS[1] += y1; accQ[1] += y1*y1;
                accS[2] += y2; accQ[2] += y2*y2;
                accS[3] += y3; accQ[3] += y3*y3;
            }
            {
                uint2 u1 = *(const uint2*)&T1p[nB*144 + f0];
                uint2 u2 = *(const uint2*)&T2p[rlB*144 + f0];
                float2 t1a = __half22float2(*(__half2*)&u1.x);
                float2 t1b = __half22float2(*(__half2*)&u1.y);
                float2 t2a = __half22float2(*(__half2*)&u2.x);
                float2 t2b = __half22float2(*(__half2*)&u2.y);
                float y0 = c[m][0][2] + t1a.x + t2a.x + bb.x;
                float y1 = c[m][0][3] + t1a.y + t2a.y + bb.y;
                float y2 = c[m][1][2] + t1b.x + t2b.x + bb.z;
                float y3 = c[m][1][3] + t1b.y + t2b.y + bb.w;
                *(uint2*)&T2p[rlB*144 + f0] = make_uint2(f2h2(y0, y1), f2h2(y2, y3));
                accS[0] += y0; accQ[0] += y0*y0;
                accS[1] += y1; accQ[1] += y1*y1;
                accS[2] += y2; accQ[2] += y2*y2;
                accS[3] += y3; accQ[3] += y3*y3;
            }
        }
        __syncthreads();
        // coalesced burst: 64 rows x 128 halfs -> full 128B-line stores
        for (int e = tid; e < 1024; e += 512) {
            int r = e >> 4, q = e & 15;
            uint4 v = *(const uint4*)&T2p[r*144 + q*8];
            *(uint4*)&g_Gh[(size_t)(r0 + r)*256 + coff + q*8] = v;
        }

        if (k == kmax) break;
    }

    // ---- BN1 partial reduction ----
#pragma unroll
    for (int off = 4; off < 32; off <<= 1) {
#pragma unroll
        for (int i = 0; i < 4; i++) {
            accS[i] += __shfl_xor_sync(0xffffffffu, accS[i], off);
            accQ[i] += __shfl_xor_sync(0xffffffffu, accQ[i], off);
        }
    }
    __syncthreads();
    if (l < 4) {
#pragma unroll
        for (int u = 0; u < 4; u++) {
            int f = wc*16 + 4*l + u;
            red_s[wr*128 + f] = accS[u];
            red_q[wr*128 + f] = accQ[u];
        }
    }
    __syncthreads();
    if (tid < 128) {
        float s = red_s[tid] + red_s[128 + tid];
        float q = red_q[tid] + red_q[128 + tid];
        g_p1s[(h*A2_SLOTS + bx)*128 + tid] = s;
        g_p1q[(h*A2_SLOTS + bx)*128 + tid] = q;
    }

    // ---- fused BN1 finalize ----
    __threadfence();
    __shared__ unsigned int s_rank;
    __syncthreads();
    if (tid == 0) s_rank = atomicAdd(&g_cnt1, 1u);
    __syncthreads();
    if (s_rank == 295u) {
        if (tid < 256) {
            const int F = tid, hh = F >> 7, fl = F & 127;
            float s = 0.f, q = 0.f;
            for (int b2 = 0; b2 < A2_SLOTS; b2++) {
                s += g_p1s[(hh*A2_SLOTS + b2)*128 + fl];
                q += g_p1q[(hh*A2_SLOTS + b2)*128 + fl];
            }
            const float mean = s * (1.0f / (float)NROWS);
            const float var  = q * (1.0f / (float)NROWS) - mean*mean;
            const float inv  = rsqrtf(var + 1e-5f);
            g_a1[F] = inv * gamma1[F];
            g_c1[F] = beta1[F] - mean * inv * gamma1[F];
        }
        __syncthreads();
        if (tid == 0) atomicExch(&g_cnt1, 0u);
    }
}

// ---------------- kernel 5: pass C (R12 version, no fused tail) ------------
__device__ __forceinline__ float sigrelu(float xf, float xc) {
    float r = fmaxf(xc, 0.f);
    float e = __expf(-xf);
    return __fdividef(r, 1.0f + e);
}

__global__ __launch_bounds__(256)
void passC_kernel() {
    __shared__ float wsum[8*128], wsq[8*128];
    const int tid = threadIdx.x, wid = tid >> 5, l = tid & 31;
    const float4 af = *(const float4*)(g_a1 + l*4);
    const float4 cf = *(const float4*)(g_c1 + l*4);
    const float4 ac = *(const float4*)(g_a1 + 128 + l*4);
    const float4 cc = *(const float4*)(g_c1 + 128 + l*4);
    float4 ts = make_float4(0.f, 0.f, 0.f, 0.f);
    float4 tq = make_float4(0.f, 0.f, 0.f, 0.f);

    for (int it = 0; it < 10; it++) {
        const int n = blockIdx.x*80 + it*8 + wid;
        float4 acc = make_float4(0.f, 0.f, 0.f, 0.f);
#pragma unroll
        for (int m = 0; m < 12; m++) {
            const size_t base = ((size_t)n*12 + m) * 256;
            uint2 uf = *(const uint2*)(g_Gh + base + l*4);
            uint2 uc = *(const uint2*)(g_Gh + base + 128 + l*4);
            float2 f01 = __half22float2(*(__half2*)&uf.x);
            float2 f23 = __half22float2(*(__half2*)&uf.y);
            float2 c01 = __half22float2(*(__half2*)&uc.x);
            float2 c23 = __half22float2(*(__half2*)&uc.y);
            acc.x += sigrelu(f01.x*af.x + cf.x, c01.x*ac.x + cc.x);
            acc.y += sigrelu(f01.y*af.y + cf.y, c01.y*ac.y + cc.y);
            acc.z += sigrelu(f23.x*af.z + cf.z, c23.x*ac.z + cc.z);
            acc.w += sigrelu(f23.y*af.w + cf.w, c23.y*ac.w + cc.w);
        }
        *(float4*)(g_S + (size_t)n*128 + l*4) = acc;
        ts.x += acc.x; ts.y += acc.y; ts.z += acc.z; ts.w += acc.w;
        tq.x += acc.x*acc.x; tq.y += acc.y*acc.y; tq.z += acc.z*acc.z; tq.w += acc.w*acc.w;
    }
    wsum[wid*128 + l*4 + 0] = ts.x; wsum[wid*128 + l*4 + 1] = ts.y;
    wsum[wid*128 + l*4 + 2] = ts.z; wsum[wid*128 + l*4 + 3] = ts.w;
    wsq [wid*128 + l*4 + 0] = tq.x; wsq [wid*128 + l*4 + 1] = tq.y;
    wsq [wid*128 + l*4 + 2] = tq.z; wsq [wid*128 + l*4 + 3] = tq.w;
    __syncthreads();
    if (tid < 128) {
        float s = 0.f, q = 0.f;
#pragma unroll
        for (int u = 0; u < 8; u++) { s += wsum[u*128 + tid]; q += wsq[u*128 + tid]; }
        g_part2[blockIdx.x*256 + tid]       = s;
        g_part2[blockIdx.x*256 + 128 + tid] = q;
    }
}

// ---------------- kernel 6: BN2 finalize (R12 version) ---------------------
__global__ void bn2fin_kernel(const float* __restrict__ gamma, const float* __restrict__ beta) {
    __shared__ float ss[1024], sq_[1024];
    const int t = threadIdx.x, col = t & 127, seg = t >> 7;
    float s = 0.f, q = 0.f;
    for (int b = seg; b < PC_BLOCKS; b += 8) {
        s += g_part2[b*256 + col];
        q += g_part2[b*256 + 128 + col];
    }
    ss[t] = s; sq_[t] = q;
    __syncthreads();
    if (seg == 0) {
        for (int u = 1; u < 8; u++) { s += ss[col + u*128]; q += sq_[col + u*128]; }
        const float mean = s * (1.0f / (float)NATOM);
        const float var  = q * (1.0f / (float)NATOM) - mean*mean;
        const float inv  = rsqrtf(var + 1e-5f);
        g_a2[col] = inv * gamma[col];
        g_c2[col] = beta[col] - mean * inv * gamma[col];
    }
}

// ---------------- kernel 7: residual + relu --------------------------------
__global__ void final_kernel(const float* __restrict__ atom, float* __restrict__ out) {
    const int i = blockIdx.x * blockDim.x + threadIdx.x;
    if (i >= NATOM * 32) return;
    const int o = (i & 31) * 4;
    const float4 a = *(const float4*)(g_a2 + o);
    const float4 c = *(const float4*)(g_c2 + o);
    const float4 v = ((const float4*)atom)[i];
    const float4 s = ((const float4*)g_S)[i];
    float4 r;
    r.x = fmaxf(v.x + s.x*a.x + c.x, 0.f);
    r.y = fmaxf(v.y + s.y*a.y + c.y, 0.f);
    r.z = fmaxf(v.z + s.z*a.z + c.z, 0.f);
    r.w = fmaxf(v.w + s.w*a.w + c.w, 0.f);
    ((float4*)out)[i] = r;
}

// ---------------- launch ----------------------------------------------------
extern "C" void kernel_launch(void* const* d_in, const int* in_sizes, int n_in,
                              void* d_out, int out_size) {
    (void)in_sizes; (void)n_in; (void)out_size;
    const float* atom = (const float*)d_in[0];
    const float* nbr  = (const float*)d_in[1];
    const void*  idx  = d_in[2];
    const float* W    = (const float*)d_in[3];
    const float* b    = (const float*)d_in[4];
    const float* g1   = (const float*)d_in[5];
    const float* b1   = (const float*)d_in[6];
    const float* g2   = (const float*)d_in[7];
    const float* b2   = (const float*)d_in[8];
    float* out = (float*)d_out;

    const int smemG1 = 2 * 128 * 136 * 2;   // 69632
    const int smemA2 = SM_A2_TOTAL;         // 111360
    cudaFuncSetAttribute(gemm1_mma, cudaFuncAttributeMaxDynamicSharedMemorySize, smemG1);
    cudaFuncSetAttribute(a2_mma,    cudaFuncAttributeMaxDynamicSharedMemorySize, smemA2);

    static cudaStream_t s1 = nullptr, s2 = nullptr;
    static cudaEvent_t ev0 = nullptr, ev1 = nullptr, ev2 = nullptr;
    if (s1 == nullptr) {
        cudaStreamCreateWithFlags(&s1, cudaStreamNonBlocking);
        cudaStreamCreateWithFlags(&s2, cudaStreamNonBlocking);
        cudaEventCreateWithFlags(&ev0, cudaEventDisableTiming);
        cudaEventCreateWithFlags(&ev1, cudaEventDisableTiming);
        cudaEventCreateWithFlags(&ev2, cudaEventDisableTiming);
    }

    cudaEventRecord(ev0, 0);
    cudaStreamWaitEvent(s1, ev0, 0);
    cudaStreamWaitEvent(s2, ev0, 0);

    pre_kernel<<<NBR_BLKS + (NROWS + 255)/256, 256, 0, s2>>>(nbr, idx);
    gemm1_mma<<<G1_TILES, 512, smemG1, s1>>>(atom, W);

    cudaEventRecord(ev1, s1);
    cudaEventRecord(ev2, s2);
    cudaStreamWaitEvent(0, ev1, 0);
    cudaStreamWaitEvent(0, ev2, 0);

    a2_mma<<<dim3(A2_SLOTS, 2), 512, smemA2>>>(W, b, g1, b1);
    passC_kernel<<<PC_BLOCKS, 256>>>();
    bn2fin_kernel<<<1, 1024>>>(g2, b2);
    final_kernel<<<12500, 256>>>(atom, out);
}

// round 16
// speedup vs baseline: 1.1139x; 1.0379x over previous
#include <cuda_runtime.h>
#include <cuda_fp16.h>
#include <cstdint>
#include <cstddef>

#define NATOM 100000
#define C2F 256
#define NROWS 1200000
#define A2_TILES 18750     /* 1.2M rows / 64 */
#define A2_SLOTS 148       /* grid.x; grid.y=2 -> 296 blocks (2/SM) */
#define G1_TILES 782       /* ceil(100000/128) */
#define PC_BLOCKS 1250
#define NBR_BLKS 75000     /* NROWS*16 float4 / 256 */

// ---------------- scratch (device globals; no allocation) ----------------
__device__ __align__(16) __half g_T1h[(size_t)NATOM*C2F];
__device__ __align__(16) __half g_T2h[(size_t)NATOM*C2F];
__device__ __align__(16) __half g_Gh[(size_t)NROWS*C2F];
__device__ __align__(16) __half g_Xh[(size_t)NROWS*64];
__device__ __align__(16) float  g_S [(size_t)NATOM*128];
__device__ int   g_idx32[NROWS];
__device__ float g_p1s[296*128], g_p1q[296*128];
__device__ float g_part2[PC_BLOCKS*256];
__device__ __align__(16) float g_a1[C2F], g_c1[C2F];
__device__ __align__(16) float g_a2[128], g_c2[128];
__device__ unsigned int g_cnt1 = 0;

// ---------------- helpers ----------------
__device__ __forceinline__ uint32_t smem_u32(const void* p) {
    uint32_t a;
    asm("{ .reg .u64 t; cvta.to.shared.u64 t, %1; cvt.u32.u64 %0, t; }" : "=r"(a) : "l"(p));
    return a;
}
__device__ __forceinline__ uint32_t f2h2(float a, float b) {
    __half2 h = __floats2half2_rn(a, b);
    return *reinterpret_cast<uint32_t*>(&h);
}
__device__ __forceinline__ void mma16(float d[4],
    uint32_t a0, uint32_t a1, uint32_t a2, uint32_t a3,
    uint32_t b0, uint32_t b1) {
    asm volatile(
        "mma.sync.aligned.m16n8k16.row.col.f32.f16.f16.f32 "
        "{%0,%1,%2,%3}, {%4,%5,%6,%7}, {%8,%9}, {%0,%1,%2,%3};"
        : "+f"(d[0]), "+f"(d[1]), "+f"(d[2]), "+f"(d[3])
        : "r"(a0), "r"(a1), "r"(a2), "r"(a3), "r"(b0), "r"(b1));
}
#define LDSM4(r0, r1, r2, r3, addr) \
    asm volatile("ldmatrix.sync.aligned.m8n8.x4.shared.b16 {%0,%1,%2,%3}, [%4];" \
        : "=r"(r0), "=r"(r1), "=r"(r2), "=r"(r3) : "r"(addr))
#define CPA16(dst, src) \
    asm volatile("cp.async.cg.shared.global [%0], [%1], 16;" :: "r"(dst), "l"(src) : "memory")
#define CPA_COMMIT() asm volatile("cp.async.commit_group;" ::: "memory")
#define CPA_WAIT0()  asm volatile("cp.async.wait_group 0;" ::: "memory")
#define CPA_WAIT1()  asm volatile("cp.async.wait_group 1;" ::: "memory")

// feature permutation within a 16-group: real offset u -> smem row offset
__device__ __forceinline__ int perm16(int u) {
    return ((u >> 1) & 1) * 8 + (u >> 2) * 2 + (u & 1);
}

// ---------------- kernel P: fused nbr->fp16 + idx convert -----------------
__global__ __launch_bounds__(256)
void pre_kernel(const float* __restrict__ nbr, const void* __restrict__ idx_raw) {
    const int b = blockIdx.x;
    if (b < NBR_BLKS) {
        const size_t i = (size_t)b * 256 + threadIdx.x;   // float4 index
        float4 x = __ldcs((const float4*)nbr + i);
        *(uint2*)(g_Xh + i*4) = make_uint2(f2h2(x.x, x.y), f2h2(x.z, x.w));
    } else {
        __shared__ int s_is64;
        if (threadIdx.x == 0) {
            const unsigned int* w = (const unsigned int*)idx_raw;
            int f = 1;
            for (int i2 = 0; i2 < 128; i2++) if (w[2*i2 + 1] != 0u) { f = 0; break; }
            s_is64 = f;
        }
        __syncthreads();
        const int i = (b - NBR_BLKS) * 256 + threadIdx.x;
        if (i < NROWS) {
            if (s_is64) g_idx32[i] = (int)((const long long*)idx_raw)[i];
            else        g_idx32[i] = ((const int*)idx_raw)[i];
        }
    }
}

// ---------------- kernel 2: GEMM1 big (y-loop inside; X staged once) -------
__global__ __launch_bounds__(512, 2)
void gemm1_mma(const float* __restrict__ atom, const float* __restrict__ W) {
    extern __shared__ char smraw[];
    __half* Xs = (__half*)smraw;                 // [128][136]
    __half* Ws = (__half*)(smraw + 128*136*2);   // [128][136] feature-permuted
    const int tid = threadIdx.x;
    const int wid = tid >> 5, l = tid & 31;
    const int l4 = l >> 2, lm = l & 3;
    const int wr = wid & 3, wc = wid >> 2;
    const int r0 = blockIdx.x * 128;

    for (int e = tid; e < 128*32; e += 512) {
        int r = e >> 5, q = e & 31;
        int gr = r0 + r;
        float4 x = make_float4(0.f, 0.f, 0.f, 0.f);
        if (gr < NATOM) x = *(const float4*)(atom + (size_t)gr*128 + q*4);
        *(uint2*)(Xs + r*136 + q*4) = make_uint2(f2h2(x.x, x.y), f2h2(x.z, x.w));
    }

    const int lrow = (l & 7) + ((l >> 3) & 1) * 8;
    const uint32_t lk = (uint32_t)((l >> 4) << 4);
    const uint32_t sX = smem_u32(Xs), sW = smem_u32(Ws);
    uint32_t aoff[2], boff[2];
    aoff[0] = sX + (uint32_t)(wr*32 + lrow) * 272u + lk;
    aoff[1] = aoff[0] + 16u * 272u;
    boff[0] = sW + (uint32_t)(wc*32 + lrow) * 272u + lk;
    boff[1] = boff[0] + 16u * 272u;

    for (int y = 0; y < 4; y++) {
        for (int e = tid; e < 128*32; e += 512) {
            int i = e >> 5, q = e & 31;
            int s = (i & ~15) + perm16(i & 15);
            const float* src = (y < 2) ? (W + (size_t)(y*128 + i)*320 + q*4)
                                       : (W + (size_t)((y - 2)*128 + i)*320 + 128 + q*4);
            float4 x = *(const float4*)src;
            *(uint2*)(Ws + s*136 + q*4) = make_uint2(f2h2(x.x, x.y), f2h2(x.z, x.w));
        }
        __syncthreads();

        float c[2][4][4];
#pragma unroll
        for (int m = 0; m < 2; m++)
#pragma unroll
            for (int n = 0; n < 4; n++)
#pragma unroll
                for (int e = 0; e < 4; e++) c[m][n][e] = 0.f;

#pragma unroll
        for (int kki = 0; kki < 8; kki++) {
            uint32_t a[2][4], b[4][2];
            LDSM4(a[0][0], a[0][1], a[0][2], a[0][3], aoff[0] + kki*32);
            LDSM4(a[1][0], a[1][1], a[1][2], a[1][3], aoff[1] + kki*32);
            LDSM4(b[0][0], b[1][0], b[0][1], b[1][1], boff[0] + kki*32);
            LDSM4(b[2][0], b[3][0], b[2][1], b[3][1], boff[1] + kki*32);
#pragma unroll
            for (int m = 0; m < 2; m++)
#pragma unroll
                for (int n = 0; n < 4; n++)
                    mma16(c[m][n], a[m][0], a[m][1], a[m][2], a[m][3], b[n][0], b[n][1]);
        }

        __half* dst = (y < 2) ? g_T1h : g_T2h;
        const int coff = (y & 1) * 128;
#pragma unroll
        for (int m = 0; m < 2; m++) {
            int rl = wr*32 + m*16 + l4;
            int gr = r0 + rl;
#pragma unroll
            for (int p = 0; p < 2; p++) {
                int cl = coff + wc*32 + p*16 + 4*lm;
                if (gr < NATOM)
                    *(uint2*)&dst[(size_t)gr*256 + cl] =
                        make_uint2(f2h2(c[m][2*p][0], c[m][2*p][1]),
                                   f2h2(c[m][2*p+1][0], c[m][2*p+1][1]));
                if (gr + 8 < NATOM)
                    *(uint2*)&dst[(size_t)(gr + 8)*256 + cl] =
                        make_uint2(f2h2(c[m][2*p][2], c[m][2*p][3]),
                                   f2h2(c[m][2*p+1][2], c[m][2*p+1][3]));
            }
        }
        __syncthreads();
    }
}

// ---------------- kernel 3: A2 — EXACT R12 configuration -------------------
#define SM_WE  0                         /* half [128][72]     = 18432 */
#define SM_X   18432                     /* half [3][64][72]   = 27648 */
#define SM_T2  46080                     /* half [3][64][144]  = 55296 */
#define SM_T1  101376                    /* half [3][8][144]   =  6912 */
#define SM_IX  108288                    /* int  [4][64]       =  1024 */
#define SM_RED 109312                    /* float[2][2][128]   =  2048 */
#define SM_A2_TOTAL 111360

__global__ __launch_bounds__(512, 2)
void a2_mma(const float* __restrict__ W, const float* __restrict__ bias,
            const float* __restrict__ gamma1, const float* __restrict__ beta1) {
    extern __shared__ char smraw[];
    __half* We  = (__half*)(smraw + SM_WE);
    float*  red_s = (float*)(smraw + SM_RED);
    float*  red_q = red_s + 256;
    const uint32_t sbase = smem_u32(smraw);

    const int tid = threadIdx.x;
    const int wid = tid >> 5, l = tid & 31;
    const int l4 = l >> 2, lm = l & 3;
    const int wr = wid & 1, wc = wid >> 1;
    const int bx = blockIdx.x, h = blockIdx.y;
    const int coff = h * 128;

    for (int e = tid; e < 128*16; e += 512) {
        int o = e >> 4, q = e & 15;
        int s = (o & ~15) + perm16(o & 15);
        float4 x = *(const float4*)(W + (size_t)(coff + o)*320 + 256 + q*4);
        *(uint2*)(We + s*72 + q*4) = make_uint2(f2h2(x.x, x.y), f2h2(x.z, x.w));
    }
    const float4 bb = *(const float4*)(bias + coff + wc*16 + 4*lm);

    const int* idxs = (const int*)(smraw + SM_IX);
    const int kmax = (A2_TILES - 1 - bx) / A2_SLOTS;

#define ISSUE_DATA(TT, BUF, IDXP) do { \
    const int _r0 = (TT) * 64; \
    const int _n0 = _r0 / 12; \
    const int _nc = (_r0 + 63) / 12 - _n0 + 1; \
    { int r = tid >> 3, q = tid & 7; \
      CPA16(sbase + SM_X + (uint32_t)(BUF)*9216u + (uint32_t)(r*144 + q*16), \
            (const char*)(g_Xh + (size_t)(_r0 + r)*64 + q*8)); } \
    for (int e = tid; e < 1024; e += 512) { \
        int r = e >> 4, q = e & 15; \
        CPA16(sbase + SM_T2 + (uint32_t)(BUF)*18432u + (uint32_t)(r*288 + q*16), \
              (const char*)(g_T2h + (size_t)(IDXP)[r]*256 + coff + q*8)); \
    } \
    for (int e = tid; e < _nc*16; e += 512) { \
        int j = e >> 4, q = e & 15; \
        CPA16(sbase + SM_T1 + (uint32_t)(BUF)*2304u + (uint32_t)(j*288 + q*16), \
              (const char*)(g_T1h + (size_t)(_n0 + j)*256 + coff + q*8)); \
    } \
} while (0)

#define ISSUE_IDX(TT, SLOT) do { \
    if (tid < 16) CPA16(sbase + SM_IX + (uint32_t)(SLOT)*256u + (uint32_t)tid*16u, \
                        (const char*)(g_idx32 + (size_t)(TT)*64) + tid*16); \
} while (0)

    ISSUE_IDX(bx, 0);
    ISSUE_IDX(bx + A2_SLOTS, 1);
    CPA_COMMIT(); CPA_WAIT0(); __syncthreads();

    ISSUE_DATA(bx, 0, idxs);
    ISSUE_IDX(bx + 2*A2_SLOTS, 2);
    CPA_COMMIT();
    ISSUE_DATA(bx + A2_SLOTS, 1, idxs + 64);
    ISSUE_IDX(bx + 3*A2_SLOTS, 3);
    CPA_COMMIT();

    uint32_t Bf[4][2][2];
#pragma unroll
    for (int kki = 0; kki < 4; kki++)
#pragma unroll
        for (int n = 0; n < 2; n++) {
            int o = wc*16 + n*8 + l4;
            Bf[kki][n][0] = *(uint32_t*)&We[o*72 + kki*16 + 2*lm];
            Bf[kki][n][1] = *(uint32_t*)&We[o*72 + kki*16 + 8 + 2*lm];
        }

    const int lrow = (l & 7) + ((l >> 3) & 1) * 8;
    const uint32_t lk = (uint32_t)((l >> 4) << 4);
    uint32_t aoff0 = (uint32_t)((wr*32 + lrow) * 144) + lk;

    float accS[4], accQ[4];
#pragma unroll
    for (int i = 0; i < 4; i++) { accS[i] = 0.f; accQ[i] = 0.f; }

    const int f0 = wc*16 + 4*lm;

    for (int k = 0; ; k++) {
        CPA_WAIT1();
        __syncthreads();

        if (k + 2 <= kmax) {
            const int tt = bx + (k + 2)*A2_SLOTS;
            ISSUE_DATA(tt, (k + 2) % 3, idxs + ((k + 2) & 3)*64);
            if (k + 4 <= kmax) ISSUE_IDX(bx + (k + 4)*A2_SLOTS, (k + 4) & 3);
        }
        CPA_COMMIT();

        const int buf = k % 3;
        const uint32_t xaddr = sbase + SM_X + (uint32_t)buf*9216u;
        const __half* T2p = (const __half*)(smraw + SM_T2 + buf*18432u);
        const __half* T1p = (const __half*)(smraw + SM_T1 + buf*2304u);
        const int r0 = (bx + k*A2_SLOTS) * 64;
        const int n0 = r0 / 12;

        float c[2][2][4];
#pragma unroll
        for (int m = 0; m < 2; m++)
#pragma unroll
            for (int n = 0; n < 2; n++)
#pragma unroll
                for (int e = 0; e < 4; e++) c[m][n][e] = 0.f;

#pragma unroll
        for (int kki = 0; kki < 4; kki++) {
            uint32_t a0, a1, a2, a3;
            LDSM4(a0, a1, a2, a3, xaddr + aoff0 + kki*32);
            mma16(c[0][0], a0, a1, a2, a3, Bf[kki][0][0], Bf[kki][0][1]);
            mma16(c[0][1], a0, a1, a2, a3, Bf[kki][1][0], Bf[kki][1][1]);
            LDSM4(a0, a1, a2, a3, xaddr + aoff0 + 16u*144u + kki*32);
            mma16(c[1][0], a0, a1, a2, a3, Bf[kki][0][0], Bf[kki][0][1]);
            mma16(c[1][1], a0, a1, a2, a3, Bf[kki][1][0], Bf[kki][1][1]);
        }

#pragma unroll
        for (int m = 0; m < 2; m++) {
            const int rlA = wr*32 + m*16 + l4;
            const int rlB = rlA + 8;
            const int nA = (r0 + rlA)/12 - n0;
            const int nB = (r0 + rlB)/12 - n0;
            {
                uint2 u1 = *(const uint2*)&T1p[nA*144 + f0];
                uint2 u2 = *(const uint2*)&T2p[rlA*144 + f0];
                float2 t1a = __half22float2(*(__half2*)&u1.x);
                float2 t1b = __half22float2(*(__half2*)&u1.y);
                float2 t2a = __half22float2(*(__half2*)&u2.x);
                float2 t2b = __half22float2(*(__half2*)&u2.y);
                float y0 = c[m][0][0] + t1a.x + t2a.x + bb.x;
                float y1 = c[m][0][1] + t1a.y + t2a.y + bb.y;
                float y2 = c[m][1][0] + t1b.x + t2b.x + bb.z;
                float y3 = c[m][1][1] + t1b.y + t2b.y + bb.w;
                *(uint2*)&g_Gh[(size_t)(r0 + rlA)*256 + coff + f0] =
                    make_uint2(f2h2(y0, y1), f2h2(y2, y3));
                accS[0] += y0; accQ[0] += y0*y0;
                accS[1] += y1; accQ[1] += y1*y1;
                accS[2] += y2; accQ[2] += y2*y2;
                accS[3] += y3; accQ[3] += y3*y3;
            }
            {
                uint2 u1 = *(const uint2*)&T1p[nB*144 + f0];
                uint2 u2 = *(const uint2*)&T2p[rlB*144 + f0];
                float2 t1a = __half22float2(*(__half2*)&u1.x);
                float2 t1b = __half22float2(*(__half2*)&u1.y);
                float2 t2a = __half22float2(*(__half2*)&u2.x);
                float2 t2b = __half22float2(*(__half2*)&u2.y);
                float y0 = c[m][0][2] + t1a.x + t2a.x + bb.x;
                float y1 = c[m][0][3] + t1a.y + t2a.y + bb.y;
                float y2 = c[m][1][2] + t1b.x + t2b.x + bb.z;
                float y3 = c[m][1][3] + t1b.y + t2b.y + bb.w;
                *(uint2*)&g_Gh[(size_t)(r0 + rlB)*256 + coff + f0] =
                    make_uint2(f2h2(y0, y1), f2h2(y2, y3));
                accS[0] += y0; accQ[0] += y0*y0;
                accS[1] += y1; accQ[1] += y1*y1;
                accS[2] += y2; accQ[2] += y2*y2;
                accS[3] += y3; accQ[3] += y3*y3;
            }
        }

        if (k == kmax) break;
    }

    // ---- BN1 partial reduction ----
#pragma unroll
    for (int off = 4; off < 32; off <<= 1) {
#pragma unroll
        for (int i = 0; i < 4; i++) {
            accS[i] += __shfl_xor_sync(0xffffffffu, accS[i], off);
            accQ[i] += __shfl_xor_sync(0xffffffffu, accQ[i], off);
        }
    }
    __syncthreads();
    if (l < 4) {
#pragma unroll
        for (int u = 0; u < 4; u++) {
            int f = wc*16 + 4*l + u;
            red_s[wr*128 + f] = accS[u];
            red_q[wr*128 + f] = accQ[u];
        }
    }
    __syncthreads();
    if (tid < 128) {
        float s = red_s[tid] + red_s[128 + tid];
        float q = red_q[tid] + red_q[128 + tid];
        g_p1s[(h*A2_SLOTS + bx)*128 + tid] = s;
        g_p1q[(h*A2_SLOTS + bx)*128 + tid] = q;
    }

    // ---- fused BN1 finalize ----
    __threadfence();
    __shared__ unsigned int s_rank;
    __syncthreads();
    if (tid == 0) s_rank = atomicAdd(&g_cnt1, 1u);
    __syncthreads();
    if (s_rank == 295u) {
        if (tid < 256) {
            const int F = tid, hh = F >> 7, fl = F & 127;
            float s = 0.f, q = 0.f;
            for (int b2 = 0; b2 < A2_SLOTS; b2++) {
                s += g_p1s[(hh*A2_SLOTS + b2)*128 + fl];
                q += g_p1q[(hh*A2_SLOTS + b2)*128 + fl];
            }
            const float mean = s * (1.0f / (float)NROWS);
            const float var  = q * (1.0f / (float)NROWS) - mean*mean;
            const float inv  = rsqrtf(var + 1e-5f);
            g_a1[F] = inv * gamma1[F];
            g_c1[F] = beta1[F] - mean * inv * gamma1[F];
        }
        __syncthreads();
        if (tid == 0) atomicExch(&g_cnt1, 0u);
    }
}

// ---------------- kernel 5: pass C (R12 + depth-4 load batching) -----------
__device__ __forceinline__ float sigrelu(float xf, float xc) {
    float r = fmaxf(xc, 0.f);
    float e = __expf(-xf);
    return __fdividef(r, 1.0f + e);
}

__global__ __launch_bounds__(256)
void passC_kernel() {
    __shared__ float wsum[8*128], wsq[8*128];
    const int tid = threadIdx.x, wid = tid >> 5, l = tid & 31;
    const float4 af = *(const float4*)(g_a1 + l*4);
    const float4 cf = *(const float4*)(g_c1 + l*4);
    const float4 ac = *(const float4*)(g_a1 + 128 + l*4);
    const float4 cc = *(const float4*)(g_c1 + 128 + l*4);
    float4 ts = make_float4(0.f, 0.f, 0.f, 0.f);
    float4 tq = make_float4(0.f, 0.f, 0.f, 0.f);

    for (int it = 0; it < 10; it++) {
        const int n = blockIdx.x*80 + it*8 + wid;
        float4 acc = make_float4(0.f, 0.f, 0.f, 0.f);
#pragma unroll
        for (int mb = 0; mb < 12; mb += 4) {
            uint2 uf[4], uc[4];
#pragma unroll
            for (int j = 0; j < 4; j++) {
                const size_t base = ((size_t)n*12 + mb + j) * 256;
                uf[j] = *(const uint2*)(g_Gh + base + l*4);
                uc[j] = *(const uint2*)(g_Gh + base + 128 + l*4);
            }
#pragma unroll
            for (int j = 0; j < 4; j++) {
                float2 f01 = __half22float2(*(__half2*)&uf[j].x);
                float2 f23 = __half22float2(*(__half2*)&uf[j].y);
                float2 c01 = __half22float2(*(__half2*)&uc[j].x);
                float2 c23 = __half22float2(*(__half2*)&uc[j].y);
                acc.x += sigrelu(f01.x*af.x + cf.x, c01.x*ac.x + cc.x);
                acc.y += sigrelu(f01.y*af.y + cf.y, c01.y*ac.y + cc.y);
                acc.z += sigrelu(f23.x*af.z + cf.z, c23.x*ac.z + cc.z);
                acc.w += sigrelu(f23.y*af.w + cf.w, c23.y*ac.w + cc.w);
            }
        }
        *(float4*)(g_S + (size_t)n*128 + l*4) = acc;
        ts.x += acc.x; ts.y += acc.y; ts.z += acc.z; ts.w += acc.w;
        tq.x += acc.x*acc.x; tq.y += acc.y*acc.y; tq.z += acc.z*acc.z; tq.w += acc.w*acc.w;
    }
    wsum[wid*128 + l*4 + 0] = ts.x; wsum[wid*128 + l*4 + 1] = ts.y;
    wsum[wid*128 + l*4 + 2] = ts.z; wsum[wid*128 + l*4 + 3] = ts.w;
    wsq [wid*128 + l*4 + 0] = tq.x; wsq [wid*128 + l*4 + 1] = tq.y;
    wsq [wid*128 + l*4 + 2] = tq.z; wsq [wid*128 + l*4 + 3] = tq.w;
    __syncthreads();
    if (tid < 128) {
        float s = 0.f, q = 0.f;
#pragma unroll
        for (int u = 0; u < 8; u++) { s += wsum[u*128 + tid]; q += wsq[u*128 + tid]; }
        g_part2[blockIdx.x*256 + tid]       = s;
        g_part2[blockIdx.x*256 + 128 + tid] = q;
    }
}

// ---------------- kernel 6: BN2 finalize (R12 version) ---------------------
__global__ void bn2fin_kernel(const float* __restrict__ gamma, const float* __restrict__ beta) {
    __shared__ float ss[1024], sq_[1024];
    const int t = threadIdx.x, col = t & 127, seg = t >> 7;
    float s = 0.f, q = 0.f;
    for (int b = seg; b < PC_BLOCKS; b += 8) {
        s += g_part2[b*256 + col];
        q += g_part2[b*256 + 128 + col];
    }
    ss[t] = s; sq_[t] = q;
    __syncthreads();
    if (seg == 0) {
        for (int u = 1; u < 8; u++) { s += ss[col + u*128]; q += sq_[col + u*128]; }
        const float mean = s * (1.0f / (float)NATOM);
        const float var  = q * (1.0f / (float)NATOM) - mean*mean;
        const float inv  = rsqrtf(var + 1e-5f);
        g_a2[col] = inv * gamma[col];
        g_c2[col] = beta[col] - mean * inv * gamma[col];
    }
}

// ---------------- kernel 7: residual + relu --------------------------------
__global__ void final_kernel(const float* __restrict__ atom, float* __restrict__ out) {
    const int i = blockIdx.x * blockDim.x + threadIdx.x;
    if (i >= NATOM * 32) return;
    const int o = (i & 31) * 4;
    const float4 a = *(const float4*)(g_a2 + o);
    const float4 c = *(const float4*)(g_c2 + o);
    const float4 v = ((const float4*)atom)[i];
    const float4 s = ((const float4*)g_S)[i];
    float4 r;
    r.x = fmaxf(v.x + s.x*a.x + c.x, 0.f);
    r.y = fmaxf(v.y + s.y*a.y + c.y, 0.f);
    r.z = fmaxf(v.z + s.z*a.z + c.z, 0.f);
    r.w = fmaxf(v.w + s.w*a.w + c.w, 0.f);
    ((float4*)out)[i] = r;
}

// ---------------- launch ----------------------------------------------------
extern "C" void kernel_launch(void* const* d_in, const int* in_sizes, int n_in,
                              void* d_out, int out_size) {
    (void)in_sizes; (void)n_in; (void)out_size;
    const float* atom = (const float*)d_in[0];
    const float* nbr  = (const float*)d_in[1];
    const void*  idx  = d_in[2];
    const float* W    = (const float*)d_in[3];
    const float* b    = (const float*)d_in[4];
    const float* g1   = (const float*)d_in[5];
    const float* b1   = (const float*)d_in[6];
    const float* g2   = (const float*)d_in[7];
    const float* b2   = (const float*)d_in[8];
    float* out = (float*)d_out;

    const int smemG1 = 2 * 128 * 136 * 2;   // 69632
    const int smemA2 = SM_A2_TOTAL;         // 111360
    cudaFuncSetAttribute(gemm1_mma, cudaFuncAttributeMaxDynamicSharedMemorySize, smemG1);
    cudaFuncSetAttribute(a2_mma,    cudaFuncAttributeMaxDynamicSharedMemorySize, smemA2);

    static cudaStream_t s1 = nullptr, s2 = nullptr;
    static cudaEvent_t ev0 = nullptr, ev1 = nullptr, ev2 = nullptr;
    if (s1 == nullptr) {
        cudaStreamCreateWithFlags(&s1, cudaStreamNonBlocking);
        cudaStreamCreateWithFlags(&s2, cudaStreamNonBlocking);
        cudaEventCreateWithFlags(&ev0, cudaEventDisableTiming);
        cudaEventCreateWithFlags(&ev1, cudaEventDisableTiming);
        cudaEventCreateWithFlags(&ev2, cudaEventDisableTiming);
    }

    cudaEventRecord(ev0, 0);
    cudaStreamWaitEvent(s1, ev0, 0);
    cudaStreamWaitEvent(s2, ev0, 0);

    pre_kernel<<<NBR_BLKS + (NROWS + 255)/256, 256, 0, s2>>>(nbr, idx);
    gemm1_mma<<<G1_TILES, 512, smemG1, s1>>>(atom, W);

    cudaEventRecord(ev1, s1);
    cudaEventRecord(ev2, s2);
    cudaStreamWaitEvent(0, ev1, 0);
    cudaStreamWaitEvent(0, ev2, 0);

    a2_mma<<<dim3(A2_SLOTS, 2), 512, smemA2>>>(W, b, g1, b1);
    passC_kernel<<<PC_BLOCKS, 256>>>();
    bn2fin_kernel<<<1, 1024>>>(g2, b2);
    final_kernel<<<12500, 256>>>(atom, out);
}